// round 12
// baseline (speedup 1.0000x reference)
#include <cuda_runtime.h>
#include <cuda_fp16.h>
#include <cstdint>

#define NN   10000
#define TT   64
#define NIN  64
#define NH   128
#define NOUT 64
#define KTOT 192
#define EMAX 160000
#define GRID_LOOP 296          // 2 CTAs/SM, co-resident for the global barrier
#define ROWS_PER_CTA 34        // ceil(10000/296)
#define NTILES 628             // 157 m-tiles (BM=64) x 4 n-tiles (BN=128)
#define ABASE  98304           // A chunk buffer after 96KB resident B
#define LOOP_SMEM 114688       // B resident 96KB + A 16KB
#define PX_BLOCKS 80000        // TT*NN/8
#define XC_BLOCKS 80000        // TT*NN*NIN/2/256

// ---------------- device scratch ----------------
__device__ float d_dinv[NN];
__device__ int   d_deg[NN];
__device__ int   d_off[NN + 1];
__device__ int   d_fill[NN];
__device__ int   d_adj[EMAX];
__device__ int   d_barCnt;
__device__ __half d_xh[(size_t)TT * NN * NIN];   // fp16 copy of x for the gather
__device__ __half d_Pxh[(size_t)TT * NN * NIN];
__device__ __half d_Pxl[(size_t)TT * NN * NIN];
__device__ __half d_Phh[NN * NH];
__device__ __half d_Phl[NN * NH];
__device__ float d_h[NN * NH];
__device__ float d_c[NN * NH];
__device__ __half d_hsbuf[2][NN * NH];           // fp16 pre-scaled hidden state
__device__ __half d_Wpk[2 * 3 * 512 * 64];  // [split][chunk64][n=j*4+g][k64]
__device__ float d_bpk[512];                 // [j*4+g]
__device__ float d_W1p[NH * 256];
__device__ float d_Wcp[NH * NOUT];
__device__ float d_HaHb[NN * 256];
__device__ float d_nodes[NN * NH];
__device__ float d_Pn[NN * NH];

// ---------------- helpers ----------------
__device__ __forceinline__ uint32_t smem_u32(const void* p) {
    uint32_t a;
    asm("{ .reg .u64 t; cvta.to.shared.u64 t, %1; cvt.u32.u64 %0, t; }" : "=r"(a) : "l"(p));
    return a;
}
__device__ __forceinline__ uint32_t pkh(__half a, __half b) {
    return (uint32_t)__half_as_ushort(a) | ((uint32_t)__half_as_ushort(b) << 16);
}
__device__ __forceinline__ float2 h2f2(uint32_t u) {
    __half2 h = *reinterpret_cast<__half2*>(&u);
    return __half22float2(h);
}
__device__ __forceinline__ void cp16(uint32_t dst, const void* src, uint32_t srcsize) {
    asm volatile("cp.async.ca.shared.global [%0], [%1], 16, %2;"
                 :: "r"(dst), "l"(src), "r"(srcsize) : "memory");
}
__device__ __forceinline__ void cp16cg(uint32_t dst, const void* src, uint32_t srcsize) {
    asm volatile("cp.async.cg.shared.global [%0], [%1], 16, %2;"
                 :: "r"(dst), "l"(src), "r"(srcsize) : "memory");
}
__device__ __forceinline__ void cp_commit() {
    asm volatile("cp.async.commit_group;" ::: "memory");
}
__device__ __forceinline__ void cp_wait0() {
    asm volatile("cp.async.wait_group 0;" ::: "memory");
}
__device__ __forceinline__ void ldsm4(uint32_t* r, uint32_t addr) {
    asm volatile("ldmatrix.sync.aligned.m8n8.x4.shared.b16 {%0,%1,%2,%3}, [%4];"
                 : "=r"(r[0]), "=r"(r[1]), "=r"(r[2]), "=r"(r[3]) : "r"(addr));
}
__device__ __forceinline__ void mma16816(float* c, const uint32_t* a, const uint32_t* b) {
    asm volatile("mma.sync.aligned.m16n8k16.row.col.f32.f16.f16.f32 "
                 "{%0,%1,%2,%3}, {%4,%5,%6,%7}, {%8,%9}, {%0,%1,%2,%3};"
                 : "+f"(c[0]), "+f"(c[1]), "+f"(c[2]), "+f"(c[3])
                 : "r"(a[0]), "r"(a[1]), "r"(a[2]), "r"(a[3]), "r"(b[0]), "r"(b[1]));
}
__device__ __forceinline__ float sigf(float x) { return 1.0f / (1.0f + __expf(-x)); }

// generation-free global barrier: monotone counter, target = bidx * GRID_LOOP
__device__ __forceinline__ void gbar(int bidx) {
    __syncthreads();
    if (threadIdx.x == 0) {
        __threadfence();
        atomicAdd(&d_barCnt, 1);
        int target = bidx * GRID_LOOP;
        int v;
        do {
            asm volatile("ld.global.cg.b32 %0, [%1];" : "=r"(v) : "l"(&d_barCnt));
            if (v < target) __nanosleep(64);
        } while (v < target);
        __threadfence();
    }
    __syncthreads();
}

// ---------------- setup kernels ----------------
__global__ void k_init() {
    int i = blockIdx.x * blockDim.x + threadIdx.x;
    if (i < NN * NH) { d_c[i] = 0.f; d_hsbuf[0][i] = __float2half_rn(0.f); }
    if (i < NN)      { d_deg[i] = 1; d_fill[i] = 0; }
    if (i == 0)      d_barCnt = 0;
}

__global__ void k_deg(const int* __restrict__ dst, int E) {
    int i = blockIdx.x * blockDim.x + threadIdx.x;
    if (i < E) atomicAdd(&d_deg[dst[i]], 1);
}

// scan (CSR offsets) + dinv in one kernel
__global__ void k_scan(int E) {
    __shared__ int ssum[1024];
    int tid = threadIdx.x;
    int loc[10]; int run = 0;
#pragma unroll
    for (int i = 0; i < 10; i++) {
        int v = tid * 10 + i;
        int c = (v < NN) ? (d_deg[v] - 1) : 0;
        loc[i] = run; run += c;
    }
    ssum[tid] = run; __syncthreads();
    for (int off = 1; off < 1024; off <<= 1) {
        int t = (tid >= off) ? ssum[tid - off] : 0;
        __syncthreads();
        ssum[tid] += t;
        __syncthreads();
    }
    int base = (tid == 0) ? 0 : ssum[tid - 1];
#pragma unroll
    for (int i = 0; i < 10; i++) {
        int v = tid * 10 + i;
        if (v < NN) {
            d_off[v] = base + loc[i];
            d_dinv[v] = rsqrtf((float)d_deg[v]);
        }
    }
    if (tid == 0) d_off[NN] = E;
}

__global__ void k_fill(const int* __restrict__ src, const int* __restrict__ dst, int E) {
    int i = blockIdx.x * blockDim.x + threadIdx.x;
    if (i < E) {
        int v = dst[i];
        int p = d_off[v] + atomicAdd(&d_fill[v], 1);
        d_adj[p] = src[i];
    }
}

// convert x to fp16 once (halves the Px gather traffic)
__global__ void k_xconv(const float* __restrict__ x) {
    size_t i = ((size_t)blockIdx.x * 256 + threadIdx.x) * 2;
    float2 v = *(const float2*)&x[i];
    *(__half2*)&d_xh[i] = __floats2half2_rn(v.x, v.y);
}

// fused: blocks < PX_BLOCKS compute Px from fp16 x (fp16 hi/lo split of the fp32 sum);
// tail blocks pack weights
#define WPK_N   196608
#define BPK_END (WPK_N + 512)
#define W1P_END (BPK_END + NH * 256)
#define WCP_END (W1P_END + NH * NOUT)
__global__ void k_pxpack(const float* __restrict__ Wi, const float* __restrict__ bi,
                         const float* __restrict__ Wf, const float* __restrict__ bf,
                         const float* __restrict__ Wo, const float* __restrict__ bo,
                         const float* __restrict__ Wg, const float* __restrict__ bg,
                         const float* __restrict__ W1, const float* __restrict__ Wc) {
    if (blockIdx.x < PX_BLOCKS) {
        int w = blockIdx.x * 8 + (threadIdx.x >> 5);
        int t = w / NN, v = w - t * NN;
        int l2 = (threadIdx.x & 31) * 2;
        const __half* xt = d_xh + (size_t)t * NN * NIN;
        float2 a = make_float2(0.f, 0.f);
        int e = d_off[v], end = d_off[v + 1];
#pragma unroll 4
        for (; e < end; e++) {
            int s = d_adj[e];
            float ds = d_dinv[s];
            float2 xv = h2f2(*(const uint32_t*)&xt[s * NIN + l2]);
            a.x += ds * xv.x; a.y += ds * xv.y;
        }
        float dv = d_dinv[v];
        float2 xs = h2f2(*(const uint32_t*)&xt[v * NIN + l2]);
        a.x = dv * (a.x + dv * xs.x);
        a.y = dv * (a.y + dv * xs.y);
        __half h0 = __float2half_rn(a.x), h1 = __float2half_rn(a.y);
        __half l0 = __float2half_rn(a.x - __half2float(h0));
        __half l1 = __float2half_rn(a.y - __half2float(h1));
        size_t o = ((size_t)t * NN + v) * NIN + l2;
        *(uint32_t*)&d_Pxh[o] = pkh(h0, h1);
        *(uint32_t*)&d_Pxl[o] = pkh(l0, l1);
    } else {
        int idx = (blockIdx.x - PX_BLOCKS) * 256 + threadIdx.x;
        if (idx < WPK_N) {
            int s = idx / 98304;
            int r = idx % 98304;
            int c = r / 32768;
            int r2 = r % 32768;
            int n = r2 >> 6, kk = r2 & 63;
            int j = n >> 2, g = n & 3, k = c * 64 + kk;
            const float* W = (g == 0) ? Wi : (g == 1) ? Wf : (g == 2) ? Wo : Wg;
            float w = W[j * KTOT + k];
            __half hi = __float2half_rn(w);
            d_Wpk[idx] = (s == 0) ? hi : __float2half_rn(w - __half2float(hi));
        } else if (idx < BPK_END) {
            int i = idx - WPK_N;
            int j = i >> 2, g = i & 3;
            const float* b = (g == 0) ? bi : (g == 1) ? bf : (g == 2) ? bo : bg;
            d_bpk[i] = b[j];
        } else if (idx < W1P_END) {
            int r = idx - BPK_END;
            int k = r / 256, cc = r % 256;
            d_W1p[r] = W1[(cc & 127) * 256 + (cc >> 7) * 128 + k];
        } else if (idx < WCP_END) {
            int r = idx - W1P_END;
            int k = r / NOUT, j = r % NOUT;
            d_Wcp[r] = Wc[j * NH + k];
        }
    }
}

// ---------------- persistent loop kernel --------------------------------------
// B (both splits, all 3 chunks, this CTA's fixed 128 n-columns) is resident in
// smem for the WHOLE 64-step loop. Only the A chunk (16KB) is streamed per tile.
__device__ __forceinline__ void loadA(uint32_t sbse, int c, int t, int m0, int tid) {
    uint32_t Ab = sbse + ABASE;
#pragma unroll
    for (int rep = 0; rep < 4; rep++) {
        int q = tid + rep * 256;
        int s = q >> 9, r = q & 511;
        int row = r >> 3, kg = r & 7;
        uint32_t ok = (m0 + row < NN) ? 16 : 0;
        uint32_t dst = Ab + s * 8192 + row * 128 + ((kg ^ (row & 7)) << 4);
        if (c == 0) {
            const __half* src = (s ? d_Pxl : d_Pxh)
                + ((size_t)t * NN + (m0 + row)) * 64 + kg * 8;
            cp16(dst, src, ok);       // Px immutable: L1-cacheable
        } else {
            const __half* src = (s ? d_Phl : d_Phh)
                + (size_t)(m0 + row) * 128 + (c - 1) * 64 + kg * 8;
            cp16cg(dst, src, ok);     // Ph changes every step: bypass L1
        }
    }
}

__global__ void __launch_bounds__(256, 2) k_loop() {
    extern __shared__ char smem[];
    const uint32_t sbse = smem_u32(smem);
    const int tid = threadIdx.x, lane = tid & 31, w = tid >> 5;
    const int cta = blockIdx.x;
    const int g = lane >> 3, lr = lane & 7;
    const int wm = (w >> 2) * 32, wn = (w & 3) * 32;
    const int n0 = (cta & 3) * 128;   // fixed n-column group for this CTA

    // ---- load resident B once: [split s][chunk c] -> sc*16KB ----
#pragma unroll
    for (int rep = 0; rep < 24; rep++) {
        int q = tid + rep * 256;
        int sc = q >> 10, r = q & 1023;
        int nr = r >> 3, kg = r & 7;
        uint32_t dst = sbse + sc * 16384 + nr * 128 + ((kg ^ (nr & 7)) << 4);
        const __half* src = d_Wpk + (size_t)(sc * 512 + n0 + nr) * 64 + kg * 8;
        cp16(dst, src, 16);
    }
    cp_commit();
    cp_wait0();
    __syncthreads();

    for (int t = 0; t < TT; t++) {
        const __half* hsr = d_hsbuf[t & 1];
        __half* hsw = d_hsbuf[(t & 1) ^ 1];

        // ---- prop phase: full-chip parallel fp16 gather, fp32 accumulate ----
        for (int rl = w; rl < ROWS_PER_CTA; rl += 8) {
            int m = cta * ROWS_PER_CTA + rl;
            if (m < NN) {
                int f4 = lane * 4;
                uint2 raw = __ldcg((const uint2*)&hsr[m * NH + f4]);
                float2 s0f = h2f2(raw.x), s1f = h2f2(raw.y);
                float4 a = make_float4(s0f.x, s0f.y, s1f.x, s1f.y);
                int e = d_off[m], end = d_off[m + 1];
                for (; e + 1 < end; e += 2) {
                    int n0i = d_adj[e], n1i = d_adj[e + 1];
                    uint2 r0 = __ldcg((const uint2*)&hsr[n0i * NH + f4]);
                    uint2 r1 = __ldcg((const uint2*)&hsr[n1i * NH + f4]);
                    float2 a0 = h2f2(r0.x), b0 = h2f2(r0.y);
                    float2 a1 = h2f2(r1.x), b1 = h2f2(r1.y);
                    a.x += a0.x + a1.x; a.y += a0.y + a1.y;
                    a.z += b0.x + b1.x; a.w += b0.y + b1.y;
                }
                if (e < end) {
                    int n0i = d_adj[e];
                    uint2 r0 = __ldcg((const uint2*)&hsr[n0i * NH + f4]);
                    float2 a0 = h2f2(r0.x), b0 = h2f2(r0.y);
                    a.x += a0.x; a.y += a0.y; a.z += b0.x; a.w += b0.y;
                }
                float dv = d_dinv[m];
                a.x *= dv; a.y *= dv; a.z *= dv; a.w *= dv;
                __half h0 = __float2half_rn(a.x), h1 = __float2half_rn(a.y);
                __half h2 = __float2half_rn(a.z), h3 = __float2half_rn(a.w);
                __half l0 = __float2half_rn(a.x - __half2float(h0));
                __half l1 = __float2half_rn(a.y - __half2float(h1));
                __half l2 = __float2half_rn(a.z - __half2float(h2));
                __half l3 = __float2half_rn(a.w - __half2float(h3));
                *(uint2*)&d_Phh[m * NH + f4] = make_uint2(pkh(h0, h1), pkh(h2, h3));
                *(uint2*)&d_Phl[m * NH + f4] = make_uint2(pkh(l0, l1), pkh(l2, l3));
            }
        }
        gbar(2 * t + 1);

        // ---- GEMM + LSTM phase (B resident; stream A chunks) ----
        for (int tile = cta; tile < NTILES; tile += GRID_LOOP) {
            int m0 = (tile >> 2) * 64;

            float acc[2][4][4];
#pragma unroll
            for (int i = 0; i < 2; i++)
#pragma unroll
                for (int j = 0; j < 4; j++)
#pragma unroll
                    for (int q = 0; q < 4; q++) acc[i][j][q] = 0.f;

#pragma unroll
            for (int c = 0; c < 3; c++) {
                loadA(sbse, c, t, m0, tid);
                cp_commit();
                cp_wait0();
                __syncthreads();
                uint32_t Ab = sbse + ABASE;
                uint32_t Bh = sbse + c * 16384;
                uint32_t Bl = sbse + (3 + c) * 16384;
#pragma unroll
                for (int ks = 0; ks < 4; ks++) {
                    uint32_t afh[2][4], afl[2][4], bfh[2][4], bfl[2][4];
#pragma unroll
                    for (int mt = 0; mt < 2; mt++) {
                        int ar = wm + mt * 16 + (g & 1) * 8 + lr;
                        int akg = ks * 2 + (g >> 1);
                        uint32_t off = ar * 128 + ((akg ^ (ar & 7)) << 4);
                        ldsm4(afh[mt], Ab + off);
                        ldsm4(afl[mt], Ab + 8192 + off);
                    }
#pragma unroll
                    for (int ns2 = 0; ns2 < 2; ns2++) {
                        int br = wn + ns2 * 16 + (g >> 1) * 8 + lr;
                        int bkg = ks * 2 + (g & 1);
                        uint32_t off = br * 128 + ((bkg ^ (br & 7)) << 4);
                        ldsm4(bfh[ns2], Bh + off);
                        ldsm4(bfl[ns2], Bl + off);
                    }
#pragma unroll
                    for (int mt = 0; mt < 2; mt++)
#pragma unroll
                        for (int nt = 0; nt < 4; nt++) {
                            mma16816(acc[mt][nt], afh[mt], &bfh[nt >> 1][(nt & 1) * 2]);
                            mma16816(acc[mt][nt], afl[mt], &bfh[nt >> 1][(nt & 1) * 2]);
                            mma16816(acc[mt][nt], afh[mt], &bfl[nt >> 1][(nt & 1) * 2]);
                        }
                }
                __syncthreads();   // before next chunk overwrites the A buffer
            }

            // shfl-exchange epilogue: even lane -> row r, odd lane -> row r+8
#pragma unroll
            for (int mt = 0; mt < 2; mt++)
#pragma unroll
                for (int nt = 0; nt < 4; nt++) {
                    int odd = lane & 1;
                    float z0 = odd ? acc[mt][nt][0] : acc[mt][nt][2];
                    float z1 = odd ? acc[mt][nt][1] : acc[mt][nt][3];
                    float w0 = __shfl_xor_sync(0xffffffffu, z0, 1);
                    float w1 = __shfl_xor_sync(0xffffffffu, z1, 1);
                    float g0, g1, g2, g3;
                    if (!odd) { g0 = acc[mt][nt][0]; g1 = acc[mt][nt][1]; g2 = w0; g3 = w1; }
                    else      { g0 = w0; g1 = w1; g2 = acc[mt][nt][2]; g3 = acc[mt][nt][3]; }
                    int m = m0 + wm + mt * 16 + (lane >> 2) + (odd ? 8 : 0);
                    if (m < NN) {
                        int j = ((n0 + wn) >> 2) + nt * 2 + ((lane & 3) >> 1);
                        float4 bb = *(const float4*)&d_bpk[j * 4];
                        float i_ = sigf(g0 + bb.x);
                        float f_ = sigf(g1 + bb.y);
                        float o_ = sigf(g2 + bb.z);
                        float gg = tanhf(g3 + bb.w);
                        int ci = m * NH + j;
                        float cn = f_ * d_c[ci] + i_ * gg;  // c is CTA-local (fixed map)
                        float hh = o_ * tanhf(cn);
                        d_c[ci] = cn;
                        hsw[ci] = __float2half_rn(d_dinv[m] * hh);
                        if (t == TT - 1) d_h[ci] = hh;
                    }
                }
        }
        gbar(2 * t + 2);
    }
}

// ---------------- decoder ----------------
__global__ void k_gemm(int sel, const float* __restrict__ bias, float* __restrict__ Cout,
                       int M, int K, int N) {
    __shared__ __align__(16) float As[16][64];
    __shared__ __align__(16) float Bs[16][64];
    const float* A = sel ? d_Pn  : d_h;
    const float* B = sel ? d_Wcp : d_W1p;
    float*       C = sel ? Cout  : d_HaHb;
    int tid = threadIdx.x;
    int tx = tid & 15, ty = tid >> 4;
    int m0 = blockIdx.x * 64, n0 = blockIdx.y * 64;
    float acc[4][4] = {};
    int lrow = tid >> 2, lkp = (tid & 3) * 4;
    int bk = tid >> 4, bcc = (tid & 15) * 4;
    for (int kc = 0; kc < K; kc += 16) {
        float4 av = make_float4(0.f, 0.f, 0.f, 0.f);
        int grow = m0 + lrow;
        if (grow < M) av = *(const float4*)&A[grow * K + kc + lkp];
        As[lkp + 0][lrow] = av.x; As[lkp + 1][lrow] = av.y;
        As[lkp + 2][lrow] = av.z; As[lkp + 3][lrow] = av.w;
        float4 bv = *(const float4*)&B[(kc + bk) * N + n0 + bcc];
        *(float4*)&Bs[bk][bcc] = bv;
        __syncthreads();
#pragma unroll
        for (int k = 0; k < 16; k++) {
            float4 a = *(const float4*)&As[k][ty * 4];
            float4 b = *(const float4*)&Bs[k][tx * 4];
            float ar[4] = {a.x, a.y, a.z, a.w};
            float br[4] = {b.x, b.y, b.z, b.w};
#pragma unroll
            for (int i = 0; i < 4; i++)
#pragma unroll
                for (int j = 0; j < 4; j++) acc[i][j] = fmaf(ar[i], br[j], acc[i][j]);
        }
        __syncthreads();
    }
    float4 bb = make_float4(0.f, 0.f, 0.f, 0.f);
    if (bias) bb = *(const float4*)&bias[n0 + tx * 4];
#pragma unroll
    for (int i = 0; i < 4; i++) {
        int m = m0 + ty * 4 + i;
        if (m >= M) continue;
        float4 o = make_float4(acc[i][0] + bb.x, acc[i][1] + bb.y,
                               acc[i][2] + bb.z, acc[i][3] + bb.w);
        *(float4*)&C[m * N + n0 + tx * 4] = o;
    }
}

__global__ void k_edge_nodes(const float* __restrict__ b1) {
    int w = blockIdx.x * 8 + (threadIdx.x >> 5);
    if (w >= NN) return;
    int l4 = (threadIdx.x & 31) * 4;
    float4 ha = *(const float4*)&d_HaHb[w * 256 + l4];
    float4 bb = *(const float4*)&b1[l4];
    ha.x += bb.x; ha.y += bb.y; ha.z += bb.z; ha.w += bb.w;
    float4 acc = make_float4(0.f, 0.f, 0.f, 0.f);
    int e = d_off[w], end = d_off[w + 1];
#pragma unroll 2
    for (; e < end; e++) {
        int s = d_adj[e];
        float4 hb = *(const float4*)&d_HaHb[s * 256 + 128 + l4];
        acc.x += fmaxf(ha.x + hb.x, 0.f);
        acc.y += fmaxf(ha.y + hb.y, 0.f);
        acc.z += fmaxf(ha.z + hb.z, 0.f);
        acc.w += fmaxf(ha.w + hb.w, 0.f);
    }
    *(float4*)&d_nodes[w * NH + l4] = acc;
}

__global__ void k_prop2() {
    int w = blockIdx.x * 8 + (threadIdx.x >> 5);
    if (w >= NN) return;
    int l4 = (threadIdx.x & 31) * 4;
    float dv = d_dinv[w];
    float4 sv = *(const float4*)&d_nodes[w * NH + l4];
    float4 acc = make_float4(dv * sv.x, dv * sv.y, dv * sv.z, dv * sv.w);
    int e = d_off[w], end = d_off[w + 1];
#pragma unroll 2
    for (; e < end; e++) {
        int s = d_adj[e];
        float ds = d_dinv[s];
        float4 v0 = *(const float4*)&d_nodes[s * NH + l4];
        acc.x += ds * v0.x; acc.y += ds * v0.y;
        acc.z += ds * v0.z; acc.w += ds * v0.w;
    }
    acc.x *= dv; acc.y *= dv; acc.z *= dv; acc.w *= dv;
    *(float4*)&d_Pn[w * NH + l4] = acc;
}

// ---------------- host launcher ----------------
extern "C" void kernel_launch(void* const* d_in, const int* in_sizes, int n_in,
                              void* d_out, int out_size) {
    const float* x  = (const float*)d_in[0];
    const int*   ei = (const int*)d_in[1];
    const int    E  = in_sizes[2];
    const int* src = ei;
    const int* dst = ei + E;
    const float* Wi = (const float*)d_in[4];
    const float* bi = (const float*)d_in[5];
    const float* Wf = (const float*)d_in[6];
    const float* bf = (const float*)d_in[7];
    const float* Wo = (const float*)d_in[8];
    const float* bo = (const float*)d_in[9];
    const float* Wg = (const float*)d_in[10];
    const float* bg = (const float*)d_in[11];
    const float* W1 = (const float*)d_in[12];
    const float* b1 = (const float*)d_in[13];
    const float* Wc = (const float*)d_in[14];
    const float* bc = (const float*)d_in[15];
    float* out = (float*)d_out;

    static int smem_set = 0;
    if (!smem_set) {
        cudaFuncSetAttribute(k_loop, cudaFuncAttributeMaxDynamicSharedMemorySize,
                             LOOP_SMEM);
        smem_set = 1;
    }

    int packBlocks = (WCP_END + 255) / 256;
    k_init<<<(NN * NH + 255) / 256, 256>>>();
    k_deg<<<(E + 255) / 256, 256>>>(dst, E);
    k_scan<<<1, 1024>>>(E);
    k_fill<<<(E + 255) / 256, 256>>>(src, dst, E);
    k_xconv<<<XC_BLOCKS, 256>>>(x);
    k_pxpack<<<PX_BLOCKS + packBlocks, 256>>>(Wi, bi, Wf, bf, Wo, bo, Wg, bg, W1, Wc);

    k_loop<<<GRID_LOOP, 256, LOOP_SMEM>>>();

    k_gemm<<<dim3((NN + 63) / 64, 4), 256>>>(0, nullptr, nullptr, NN, NH, 256);
    k_edge_nodes<<<NN / 8, 256>>>(b1);
    k_prop2<<<NN / 8, 256>>>();
    k_gemm<<<dim3((NN + 63) / 64, 1), 256>>>(1, bc, out, NN, NH, NOUT);
}

// round 13
// speedup vs baseline: 1.0900x; 1.0900x over previous
#include <cuda_runtime.h>
#include <cuda_fp16.h>
#include <cstdint>

#define NN   10000
#define TT   64
#define NIN  64
#define NH   128
#define NOUT 64
#define KTOT 192
#define EMAX 160000
#define GRID_LOOP 296          // 2 CTAs/SM, co-resident for the global barrier
#define ROWS_PER_CTA 34        // ceil(10000/296)
#define NTILES 1256            // 157 m-tiles (BM=64) x 8 n-tiles (BN=64)
#define ABASE  49152           // A double-buffer after 48KB resident B
#define LOOP_SMEM 81920        // B resident 48KB + A 2x16KB
#define PX_BLOCKS 80000        // TT*NN/8
#define XC_BLOCKS 80000        // TT*NN*NIN/2/256

// ---------------- device scratch ----------------
__device__ float d_dinv[NN];
__device__ int   d_deg[NN];
__device__ int   d_off[NN + 1];
__device__ int   d_fill[NN];
__device__ int   d_adj[EMAX];
__device__ int   d_barCnt;
__device__ __half d_xh[(size_t)TT * NN * NIN];   // fp16 copy of x for the gather
__device__ __half d_Pxh[(size_t)TT * NN * NIN];
__device__ __half d_Pxl[(size_t)TT * NN * NIN];
__device__ __half d_Phh[NN * NH];
__device__ __half d_Phl[NN * NH];
__device__ float d_h[NN * NH];
__device__ float d_c[NN * NH];
__device__ __half d_hsbuf[2][NN * NH];           // fp16 pre-scaled hidden state
__device__ __half d_Wpk[2 * 3 * 512 * 64];  // [split][chunk64][n=j*4+g][k64]
__device__ float d_bpk[512];                 // [j*4+g]
__device__ float d_W1p[NH * 256];
__device__ float d_Wcp[NH * NOUT];
__device__ float d_HaHb[NN * 256];
__device__ float d_nodes[NN * NH];
__device__ float d_Pn[NN * NH];

// ---------------- helpers ----------------
__device__ __forceinline__ uint32_t smem_u32(const void* p) {
    uint32_t a;
    asm("{ .reg .u64 t; cvta.to.shared.u64 t, %1; cvt.u32.u64 %0, t; }" : "=r"(a) : "l"(p));
    return a;
}
__device__ __forceinline__ uint32_t pkh(__half a, __half b) {
    return (uint32_t)__half_as_ushort(a) | ((uint32_t)__half_as_ushort(b) << 16);
}
__device__ __forceinline__ float2 h2f2(uint32_t u) {
    __half2 h = *reinterpret_cast<__half2*>(&u);
    return __half22float2(h);
}
__device__ __forceinline__ void cp16(uint32_t dst, const void* src, uint32_t srcsize) {
    asm volatile("cp.async.ca.shared.global [%0], [%1], 16, %2;"
                 :: "r"(dst), "l"(src), "r"(srcsize) : "memory");
}
__device__ __forceinline__ void cp16cg(uint32_t dst, const void* src, uint32_t srcsize) {
    asm volatile("cp.async.cg.shared.global [%0], [%1], 16, %2;"
                 :: "r"(dst), "l"(src), "r"(srcsize) : "memory");
}
__device__ __forceinline__ void cp_commit() {
    asm volatile("cp.async.commit_group;" ::: "memory");
}
__device__ __forceinline__ void cp_wait1() {
    asm volatile("cp.async.wait_group 1;" ::: "memory");
}
__device__ __forceinline__ void cp_wait0() {
    asm volatile("cp.async.wait_group 0;" ::: "memory");
}
__device__ __forceinline__ void ldsm4(uint32_t* r, uint32_t addr) {
    asm volatile("ldmatrix.sync.aligned.m8n8.x4.shared.b16 {%0,%1,%2,%3}, [%4];"
                 : "=r"(r[0]), "=r"(r[1]), "=r"(r[2]), "=r"(r[3]) : "r"(addr));
}
__device__ __forceinline__ void mma16816(float* c, const uint32_t* a, const uint32_t* b) {
    asm volatile("mma.sync.aligned.m16n8k16.row.col.f32.f16.f16.f32 "
                 "{%0,%1,%2,%3}, {%4,%5,%6,%7}, {%8,%9}, {%0,%1,%2,%3};"
                 : "+f"(c[0]), "+f"(c[1]), "+f"(c[2]), "+f"(c[3])
                 : "r"(a[0]), "r"(a[1]), "r"(a[2]), "r"(a[3]), "r"(b[0]), "r"(b[1]));
}
__device__ __forceinline__ float sigf(float x) { return 1.0f / (1.0f + __expf(-x)); }

// generation-free global barrier: monotone counter, target = bidx * GRID_LOOP
__device__ __forceinline__ void gbar(int bidx) {
    __syncthreads();
    if (threadIdx.x == 0) {
        __threadfence();
        atomicAdd(&d_barCnt, 1);
        int target = bidx * GRID_LOOP;
        int v;
        do {
            asm volatile("ld.global.cg.b32 %0, [%1];" : "=r"(v) : "l"(&d_barCnt));
            if (v < target) __nanosleep(64);
        } while (v < target);
        __threadfence();
    }
    __syncthreads();
}

// ---------------- setup kernels ----------------
__global__ void k_init() {
    int i = blockIdx.x * blockDim.x + threadIdx.x;
    if (i < NN * NH) { d_c[i] = 0.f; d_hsbuf[0][i] = __float2half_rn(0.f); }
    if (i < NN)      { d_deg[i] = 1; d_fill[i] = 0; }
    if (i == 0)      d_barCnt = 0;
}

__global__ void k_deg(const int* __restrict__ dst, int E) {
    int i = blockIdx.x * blockDim.x + threadIdx.x;
    if (i < E) atomicAdd(&d_deg[dst[i]], 1);
}

// scan (CSR offsets) + dinv in one kernel
__global__ void k_scan(int E) {
    __shared__ int ssum[1024];
    int tid = threadIdx.x;
    int loc[10]; int run = 0;
#pragma unroll
    for (int i = 0; i < 10; i++) {
        int v = tid * 10 + i;
        int c = (v < NN) ? (d_deg[v] - 1) : 0;
        loc[i] = run; run += c;
    }
    ssum[tid] = run; __syncthreads();
    for (int off = 1; off < 1024; off <<= 1) {
        int t = (tid >= off) ? ssum[tid - off] : 0;
        __syncthreads();
        ssum[tid] += t;
        __syncthreads();
    }
    int base = (tid == 0) ? 0 : ssum[tid - 1];
#pragma unroll
    for (int i = 0; i < 10; i++) {
        int v = tid * 10 + i;
        if (v < NN) {
            d_off[v] = base + loc[i];
            d_dinv[v] = rsqrtf((float)d_deg[v]);
        }
    }
    if (tid == 0) d_off[NN] = E;
}

__global__ void k_fill(const int* __restrict__ src, const int* __restrict__ dst, int E) {
    int i = blockIdx.x * blockDim.x + threadIdx.x;
    if (i < E) {
        int v = dst[i];
        int p = d_off[v] + atomicAdd(&d_fill[v], 1);
        d_adj[p] = src[i];
    }
}

// convert x to fp16 once (halves the Px gather traffic)
__global__ void k_xconv(const float* __restrict__ x) {
    size_t i = ((size_t)blockIdx.x * 256 + threadIdx.x) * 2;
    float2 v = *(const float2*)&x[i];
    *(__half2*)&d_xh[i] = __floats2half2_rn(v.x, v.y);
}

// fused: blocks < PX_BLOCKS compute Px from fp16 x (fp16 hi/lo split of the fp32 sum);
// tail blocks pack weights
#define WPK_N   196608
#define BPK_END (WPK_N + 512)
#define W1P_END (BPK_END + NH * 256)
#define WCP_END (W1P_END + NH * NOUT)
__global__ void k_pxpack(const float* __restrict__ Wi, const float* __restrict__ bi,
                         const float* __restrict__ Wf, const float* __restrict__ bf,
                         const float* __restrict__ Wo, const float* __restrict__ bo,
                         const float* __restrict__ Wg, const float* __restrict__ bg,
                         const float* __restrict__ W1, const float* __restrict__ Wc) {
    if (blockIdx.x < PX_BLOCKS) {
        int w = blockIdx.x * 8 + (threadIdx.x >> 5);
        int t = w / NN, v = w - t * NN;
        int l2 = (threadIdx.x & 31) * 2;
        const __half* xt = d_xh + (size_t)t * NN * NIN;
        float2 a = make_float2(0.f, 0.f);
        int e = d_off[v], end = d_off[v + 1];
#pragma unroll 4
        for (; e < end; e++) {
            int s = d_adj[e];
            float ds = d_dinv[s];
            float2 xv = h2f2(*(const uint32_t*)&xt[s * NIN + l2]);
            a.x += ds * xv.x; a.y += ds * xv.y;
        }
        float dv = d_dinv[v];
        float2 xs = h2f2(*(const uint32_t*)&xt[v * NIN + l2]);
        a.x = dv * (a.x + dv * xs.x);
        a.y = dv * (a.y + dv * xs.y);
        __half h0 = __float2half_rn(a.x), h1 = __float2half_rn(a.y);
        __half l0 = __float2half_rn(a.x - __half2float(h0));
        __half l1 = __float2half_rn(a.y - __half2float(h1));
        size_t o = ((size_t)t * NN + v) * NIN + l2;
        *(uint32_t*)&d_Pxh[o] = pkh(h0, h1);
        *(uint32_t*)&d_Pxl[o] = pkh(l0, l1);
    } else {
        int idx = (blockIdx.x - PX_BLOCKS) * 256 + threadIdx.x;
        if (idx < WPK_N) {
            int s = idx / 98304;
            int r = idx % 98304;
            int c = r / 32768;
            int r2 = r % 32768;
            int n = r2 >> 6, kk = r2 & 63;
            int j = n >> 2, g = n & 3, k = c * 64 + kk;
            const float* W = (g == 0) ? Wi : (g == 1) ? Wf : (g == 2) ? Wo : Wg;
            float w = W[j * KTOT + k];
            __half hi = __float2half_rn(w);
            d_Wpk[idx] = (s == 0) ? hi : __float2half_rn(w - __half2float(hi));
        } else if (idx < BPK_END) {
            int i = idx - WPK_N;
            int j = i >> 2, g = i & 3;
            const float* b = (g == 0) ? bi : (g == 1) ? bf : (g == 2) ? bo : bg;
            d_bpk[i] = b[j];
        } else if (idx < W1P_END) {
            int r = idx - BPK_END;
            int k = r / 256, cc = r % 256;
            d_W1p[r] = W1[(cc & 127) * 256 + (cc >> 7) * 128 + k];
        } else if (idx < WCP_END) {
            int r = idx - W1P_END;
            int k = r / NOUT, j = r % NOUT;
            d_Wcp[r] = Wc[j * NH + k];
        }
    }
}

// ---------------- persistent loop kernel --------------------------------------
// Resident B: this CTA's fixed 64 n-columns, both splits, all 3 chunks (48KB).
// A chunks (16KB: hi 8K + lo 8K) are double-buffered per tile.
__device__ __forceinline__ void loadA(uint32_t sbse, int buf, int c, int t,
                                      int m0, int tid) {
    uint32_t Ab = sbse + ABASE + buf * 16384;
#pragma unroll
    for (int rep = 0; rep < 4; rep++) {
        int q = tid + rep * 256;
        int s = q >> 9, r = q & 511;
        int row = r >> 3, kg = r & 7;
        uint32_t ok = (m0 + row < NN) ? 16 : 0;
        uint32_t dst = Ab + s * 8192 + row * 128 + ((kg ^ (row & 7)) << 4);
        if (c == 0) {
            const __half* src = (s ? d_Pxl : d_Pxh)
                + ((size_t)t * NN + (m0 + row)) * 64 + kg * 8;
            cp16(dst, src, ok);       // Px immutable: L1-cacheable
        } else {
            const __half* src = (s ? d_Phl : d_Phh)
                + (size_t)(m0 + row) * 128 + (c - 1) * 64 + kg * 8;
            cp16cg(dst, src, ok);     // Ph changes every step: bypass L1
        }
    }
}

__global__ void __launch_bounds__(256, 2) k_loop() {
    extern __shared__ char smem[];
    const uint32_t sbse = smem_u32(smem);
    const int tid = threadIdx.x, lane = tid & 31, w = tid >> 5;
    const int cta = blockIdx.x;
    const int g = lane >> 3, lr = lane & 7;
    const int wm = (w >> 1) * 16, wn = (w & 1) * 32;
    const int n0 = (cta & 7) * 64;    // fixed 64 gate-columns for this CTA
    const int jbase = (n0 + wn) >> 2;

    // ---- load resident B once: [sc = s*3+c] -> sc*8KB, 64n x 64k swizzled ----
#pragma unroll
    for (int rep = 0; rep < 12; rep++) {
        int q = tid + rep * 256;
        int sc = q >> 9, r = q & 511;
        int nr = r >> 3, kg = r & 7;
        uint32_t dst = sbse + sc * 8192 + nr * 128 + ((kg ^ (nr & 7)) << 4);
        const __half* src = d_Wpk + (size_t)(sc * 512 + n0 + nr) * 64 + kg * 8;
        cp16(dst, src, 16);
    }
    cp_commit();
    cp_wait0();
    __syncthreads();

    for (int t = 0; t < TT; t++) {
        const __half* hsr = d_hsbuf[t & 1];
        __half* hsw = d_hsbuf[(t & 1) ^ 1];

        // ---- prop phase: full-chip parallel fp16 gather, fp32 accumulate ----
        for (int rl = w; rl < ROWS_PER_CTA; rl += 8) {
            int m = cta * ROWS_PER_CTA + rl;
            if (m < NN) {
                int f4 = lane * 4;
                uint2 raw = __ldcg((const uint2*)&hsr[m * NH + f4]);
                float2 s0f = h2f2(raw.x), s1f = h2f2(raw.y);
                float4 a = make_float4(s0f.x, s0f.y, s1f.x, s1f.y);
                int e = d_off[m], end = d_off[m + 1];
                for (; e + 1 < end; e += 2) {
                    int n0i = d_adj[e], n1i = d_adj[e + 1];
                    uint2 r0 = __ldcg((const uint2*)&hsr[n0i * NH + f4]);
                    uint2 r1 = __ldcg((const uint2*)&hsr[n1i * NH + f4]);
                    float2 a0 = h2f2(r0.x), b0 = h2f2(r0.y);
                    float2 a1 = h2f2(r1.x), b1 = h2f2(r1.y);
                    a.x += a0.x + a1.x; a.y += a0.y + a1.y;
                    a.z += b0.x + b1.x; a.w += b0.y + b1.y;
                }
                if (e < end) {
                    int n0i = d_adj[e];
                    uint2 r0 = __ldcg((const uint2*)&hsr[n0i * NH + f4]);
                    float2 a0 = h2f2(r0.x), b0 = h2f2(r0.y);
                    a.x += a0.x; a.y += a0.y; a.z += b0.x; a.w += b0.y;
                }
                float dv = d_dinv[m];
                a.x *= dv; a.y *= dv; a.z *= dv; a.w *= dv;
                __half h0 = __float2half_rn(a.x), h1 = __float2half_rn(a.y);
                __half h2 = __float2half_rn(a.z), h3 = __float2half_rn(a.w);
                __half l0 = __float2half_rn(a.x - __half2float(h0));
                __half l1 = __float2half_rn(a.y - __half2float(h1));
                __half l2 = __float2half_rn(a.z - __half2float(h2));
                __half l3 = __float2half_rn(a.w - __half2float(h3));
                *(uint2*)&d_Phh[m * NH + f4] = make_uint2(pkh(h0, h1), pkh(h2, h3));
                *(uint2*)&d_Phl[m * NH + f4] = make_uint2(pkh(l0, l1), pkh(l2, l3));
            }
        }
        gbar(2 * t + 1);

        // ---- GEMM + LSTM phase (B resident; A double-buffered) ----
        for (int tile = cta; tile < NTILES; tile += GRID_LOOP) {
            int m0 = (tile >> 3) * 64;

            float acc[4][4];
#pragma unroll
            for (int j = 0; j < 4; j++)
#pragma unroll
                for (int q = 0; q < 4; q++) acc[j][q] = 0.f;

            loadA(sbse, 0, 0, t, m0, tid); cp_commit();
            loadA(sbse, 1, 1, t, m0, tid); cp_commit();

#pragma unroll
            for (int c = 0; c < 3; c++) {
                if (c < 2) cp_wait1(); else cp_wait0();
                __syncthreads();
                uint32_t Ab = sbse + ABASE + (c & 1) * 16384;
                uint32_t Bh = sbse + c * 8192;
                uint32_t Bl = sbse + (3 + c) * 8192;
#pragma unroll
                for (int ks = 0; ks < 4; ks++) {
                    uint32_t afh[4], afl[4], bfh[2][4], bfl[2][4];
                    {
                        int ar = wm + (g & 1) * 8 + lr;
                        int akg = ks * 2 + (g >> 1);
                        uint32_t off = ar * 128 + ((akg ^ (ar & 7)) << 4);
                        ldsm4(afh, Ab + off);
                        ldsm4(afl, Ab + 8192 + off);
                    }
#pragma unroll
                    for (int ns2 = 0; ns2 < 2; ns2++) {
                        int br = wn + ns2 * 16 + (g >> 1) * 8 + lr;
                        int bkg = ks * 2 + (g & 1);
                        uint32_t off = br * 128 + ((bkg ^ (br & 7)) << 4);
                        ldsm4(bfh[ns2], Bh + off);
                        ldsm4(bfl[ns2], Bl + off);
                    }
#pragma unroll
                    for (int nt = 0; nt < 4; nt++) {
                        mma16816(acc[nt], afh, &bfh[nt >> 1][(nt & 1) * 2]);
                        mma16816(acc[nt], afl, &bfh[nt >> 1][(nt & 1) * 2]);
                        mma16816(acc[nt], afh, &bfl[nt >> 1][(nt & 1) * 2]);
                    }
                }
                __syncthreads();
                if (c == 0) { loadA(sbse, 0, 2, t, m0, tid); cp_commit(); }
            }

            // shfl-exchange epilogue: even lane -> row r, odd lane -> row r+8
#pragma unroll
            for (int nt = 0; nt < 4; nt++) {
                int odd = lane & 1;
                float z0 = odd ? acc[nt][0] : acc[nt][2];
                float z1 = odd ? acc[nt][1] : acc[nt][3];
                float w0 = __shfl_xor_sync(0xffffffffu, z0, 1);
                float w1 = __shfl_xor_sync(0xffffffffu, z1, 1);
                float g0, g1, g2, g3;
                if (!odd) { g0 = acc[nt][0]; g1 = acc[nt][1]; g2 = w0; g3 = w1; }
                else      { g0 = w0; g1 = w1; g2 = acc[nt][2]; g3 = acc[nt][3]; }
                int m = m0 + wm + (lane >> 2) + (odd ? 8 : 0);
                if (m < NN) {
                    int j = jbase + nt * 2 + ((lane & 3) >> 1);
                    float4 bb = *(const float4*)&d_bpk[j * 4];
                    float i_ = sigf(g0 + bb.x);
                    float f_ = sigf(g1 + bb.y);
                    float o_ = sigf(g2 + bb.z);
                    float gg = tanhf(g3 + bb.w);
                    int ci = m * NH + j;
                    float cn = f_ * d_c[ci] + i_ * gg;  // c is CTA-local (fixed map)
                    float hh = o_ * tanhf(cn);
                    d_c[ci] = cn;
                    hsw[ci] = __float2half_rn(d_dinv[m] * hh);
                    if (t == TT - 1) d_h[ci] = hh;
                }
            }
        }
        gbar(2 * t + 2);
    }
}

// ---------------- decoder ----------------
__global__ void k_gemm(int sel, const float* __restrict__ bias, float* __restrict__ Cout,
                       int M, int K, int N) {
    __shared__ __align__(16) float As[16][64];
    __shared__ __align__(16) float Bs[16][64];
    const float* A = sel ? d_Pn  : d_h;
    const float* B = sel ? d_Wcp : d_W1p;
    float*       C = sel ? Cout  : d_HaHb;
    int tid = threadIdx.x;
    int tx = tid & 15, ty = tid >> 4;
    int m0 = blockIdx.x * 64, n0 = blockIdx.y * 64;
    float acc[4][4] = {};
    int lrow = tid >> 2, lkp = (tid & 3) * 4;
    int bk = tid >> 4, bcc = (tid & 15) * 4;
    for (int kc = 0; kc < K; kc += 16) {
        float4 av = make_float4(0.f, 0.f, 0.f, 0.f);
        int grow = m0 + lrow;
        if (grow < M) av = *(const float4*)&A[grow * K + kc + lkp];
        As[lkp + 0][lrow] = av.x; As[lkp + 1][lrow] = av.y;
        As[lkp + 2][lrow] = av.z; As[lkp + 3][lrow] = av.w;
        float4 bv = *(const float4*)&B[(kc + bk) * N + n0 + bcc];
        *(float4*)&Bs[bk][bcc] = bv;
        __syncthreads();
#pragma unroll
        for (int k = 0; k < 16; k++) {
            float4 a = *(const float4*)&As[k][ty * 4];
            float4 b = *(const float4*)&Bs[k][tx * 4];
            float ar[4] = {a.x, a.y, a.z, a.w};
            float br[4] = {b.x, b.y, b.z, b.w};
#pragma unroll
            for (int i = 0; i < 4; i++)
#pragma unroll
                for (int j = 0; j < 4; j++) acc[i][j] = fmaf(ar[i], br[j], acc[i][j]);
        }
        __syncthreads();
    }
    float4 bb = make_float4(0.f, 0.f, 0.f, 0.f);
    if (bias) bb = *(const float4*)&bias[n0 + tx * 4];
#pragma unroll
    for (int i = 0; i < 4; i++) {
        int m = m0 + ty * 4 + i;
        if (m >= M) continue;
        float4 o = make_float4(acc[i][0] + bb.x, acc[i][1] + bb.y,
                               acc[i][2] + bb.z, acc[i][3] + bb.w);
        *(float4*)&C[m * N + n0 + tx * 4] = o;
    }
}

__global__ void k_edge_nodes(const float* __restrict__ b1) {
    int w = blockIdx.x * 8 + (threadIdx.x >> 5);
    if (w >= NN) return;
    int l4 = (threadIdx.x & 31) * 4;
    float4 ha = *(const float4*)&d_HaHb[w * 256 + l4];
    float4 bb = *(const float4*)&b1[l4];
    ha.x += bb.x; ha.y += bb.y; ha.z += bb.z; ha.w += bb.w;
    float4 acc = make_float4(0.f, 0.f, 0.f, 0.f);
    int e = d_off[w], end = d_off[w + 1];
#pragma unroll 2
    for (; e < end; e++) {
        int s = d_adj[e];
        float4 hb = *(const float4*)&d_HaHb[s * 256 + 128 + l4];
        acc.x += fmaxf(ha.x + hb.x, 0.f);
        acc.y += fmaxf(ha.y + hb.y, 0.f);
        acc.z += fmaxf(ha.z + hb.z, 0.f);
        acc.w += fmaxf(ha.w + hb.w, 0.f);
    }
    *(float4*)&d_nodes[w * NH + l4] = acc;
}

__global__ void k_prop2() {
    int w = blockIdx.x * 8 + (threadIdx.x >> 5);
    if (w >= NN) return;
    int l4 = (threadIdx.x & 31) * 4;
    float dv = d_dinv[w];
    float4 sv = *(const float4*)&d_nodes[w * NH + l4];
    float4 acc = make_float4(dv * sv.x, dv * sv.y, dv * sv.z, dv * sv.w);
    int e = d_off[w], end = d_off[w + 1];
#pragma unroll 2
    for (; e < end; e++) {
        int s = d_adj[e];
        float ds = d_dinv[s];
        float4 v0 = *(const float4*)&d_nodes[s * NH + l4];
        acc.x += ds * v0.x; acc.y += ds * v0.y;
        acc.z += ds * v0.z; acc.w += ds * v0.w;
    }
    acc.x *= dv; acc.y *= dv; acc.z *= dv; acc.w *= dv;
    *(float4*)&d_Pn[w * NH + l4] = acc;
}

// ---------------- host launcher ----------------
extern "C" void kernel_launch(void* const* d_in, const int* in_sizes, int n_in,
                              void* d_out, int out_size) {
    const float* x  = (const float*)d_in[0];
    const int*   ei = (const int*)d_in[1];
    const int    E  = in_sizes[2];
    const int* src = ei;
    const int* dst = ei + E;
    const float* Wi = (const float*)d_in[4];
    const float* bi = (const float*)d_in[5];
    const float* Wf = (const float*)d_in[6];
    const float* bf = (const float*)d_in[7];
    const float* Wo = (const float*)d_in[8];
    const float* bo = (const float*)d_in[9];
    const float* Wg = (const float*)d_in[10];
    const float* bg = (const float*)d_in[11];
    const float* W1 = (const float*)d_in[12];
    const float* b1 = (const float*)d_in[13];
    const float* Wc = (const float*)d_in[14];
    const float* bc = (const float*)d_in[15];
    float* out = (float*)d_out;

    static int smem_set = 0;
    if (!smem_set) {
        cudaFuncSetAttribute(k_loop, cudaFuncAttributeMaxDynamicSharedMemorySize,
                             LOOP_SMEM);
        smem_set = 1;
    }

    int packBlocks = (WCP_END + 255) / 256;
    k_init<<<(NN * NH + 255) / 256, 256>>>();
    k_deg<<<(E + 255) / 256, 256>>>(dst, E);
    k_scan<<<1, 1024>>>(E);
    k_fill<<<(E + 255) / 256, 256>>>(src, dst, E);
    k_xconv<<<XC_BLOCKS, 256>>>(x);
    k_pxpack<<<PX_BLOCKS + packBlocks, 256>>>(Wi, bi, Wf, bf, Wo, bo, Wg, bg, W1, Wc);

    k_loop<<<GRID_LOOP, 256, LOOP_SMEM>>>();

    k_gemm<<<dim3((NN + 63) / 64, 4), 256>>>(0, nullptr, nullptr, NN, NH, 256);
    k_edge_nodes<<<NN / 8, 256>>>(b1);
    k_prop2<<<NN / 8, 256>>>();
    k_gemm<<<dim3((NN + 63) / 64, 1), 256>>>(1, bc, out, NN, NH, NOUT);
}

// round 14
// speedup vs baseline: 1.1713x; 1.0746x over previous
#include <cuda_runtime.h>
#include <cuda_fp16.h>
#include <cstdint>

#define NN   10000
#define TT   64
#define NIN  64
#define NH   128
#define NOUT 64
#define KTOT 192
#define EMAX 160000
#define GRID_LOOP 296          // 2 CTAs/SM, co-resident for the global barrier
#define ROWS_PER_CTA 34        // ceil(10000/296)
#define NTILES 628             // 157 m-tiles (BM=64) x 4 n-tiles (BN=128)
#define STAGE_BYTES 49152      // Ah 8K | Al 8K | Bh 16K | Bl 16K
#define LOOP_SMEM 98304        // 2 stage buffers; epilogue reuses buffer 0
#define PX_BLOCKS 80000        // TT*NN/8
#define XC_BLOCKS 80000        // TT*NN*NIN/2/256

// ---------------- device scratch ----------------
__device__ float d_dinv[NN];
__device__ int   d_deg[NN];
__device__ int   d_off[NN + 1];
__device__ int   d_fill[NN];
__device__ int   d_adj[EMAX];
__device__ int   d_barCnt;
__device__ __half d_xh[(size_t)TT * NN * NIN];   // fp16 copy of x for the gather
__device__ __half d_Pxh[(size_t)TT * NN * NIN];
__device__ __half d_Pxl[(size_t)TT * NN * NIN];
__device__ __half d_Phh[NN * NH];
__device__ __half d_Phl[NN * NH];
__device__ float d_h[NN * NH];
__device__ float d_c[NN * NH];
__device__ __half d_hsbuf[2][NN * NH];           // fp16 pre-scaled hidden state
__device__ __half d_Wpk[2 * 3 * 512 * 64];  // [split][chunk64][n=j*4+g][k64]
__device__ float d_bpk[512];                 // [j*4+g]
__device__ float d_W1p[NH * 256];
__device__ float d_Wcp[NH * NOUT];
__device__ float d_HaHb[NN * 256];
__device__ float d_nodes[NN * NH];
__device__ float d_Pn[NN * NH];

// ---------------- helpers ----------------
__device__ __forceinline__ uint32_t smem_u32(const void* p) {
    uint32_t a;
    asm("{ .reg .u64 t; cvta.to.shared.u64 t, %1; cvt.u32.u64 %0, t; }" : "=r"(a) : "l"(p));
    return a;
}
__device__ __forceinline__ uint32_t pkh(__half a, __half b) {
    return (uint32_t)__half_as_ushort(a) | ((uint32_t)__half_as_ushort(b) << 16);
}
__device__ __forceinline__ float2 h2f2(uint32_t u) {
    __half2 h = *reinterpret_cast<__half2*>(&u);
    return __half22float2(h);
}
__device__ __forceinline__ void cp16(uint32_t dst, const void* src, uint32_t srcsize) {
    asm volatile("cp.async.ca.shared.global [%0], [%1], 16, %2;"
                 :: "r"(dst), "l"(src), "r"(srcsize) : "memory");
}
__device__ __forceinline__ void cp16cg(uint32_t dst, const void* src, uint32_t srcsize) {
    asm volatile("cp.async.cg.shared.global [%0], [%1], 16, %2;"
                 :: "r"(dst), "l"(src), "r"(srcsize) : "memory");
}
__device__ __forceinline__ void cp_commit() {
    asm volatile("cp.async.commit_group;" ::: "memory");
}
__device__ __forceinline__ void cp_wait1() {
    asm volatile("cp.async.wait_group 1;" ::: "memory");
}
__device__ __forceinline__ void cp_wait0() {
    asm volatile("cp.async.wait_group 0;" ::: "memory");
}
__device__ __forceinline__ void ldsm4(uint32_t* r, uint32_t addr) {
    asm volatile("ldmatrix.sync.aligned.m8n8.x4.shared.b16 {%0,%1,%2,%3}, [%4];"
                 : "=r"(r[0]), "=r"(r[1]), "=r"(r[2]), "=r"(r[3]) : "r"(addr));
}
__device__ __forceinline__ void mma16816(float* c, const uint32_t* a, const uint32_t* b) {
    asm volatile("mma.sync.aligned.m16n8k16.row.col.f32.f16.f16.f32 "
                 "{%0,%1,%2,%3}, {%4,%5,%6,%7}, {%8,%9}, {%0,%1,%2,%3};"
                 : "+f"(c[0]), "+f"(c[1]), "+f"(c[2]), "+f"(c[3])
                 : "r"(a[0]), "r"(a[1]), "r"(a[2]), "r"(a[3]), "r"(b[0]), "r"(b[1]));
}
__device__ __forceinline__ float sigf(float x) { return 1.0f / (1.0f + __expf(-x)); }

// generation-free global barrier: monotone counter, target = bidx * GRID_LOOP
__device__ __forceinline__ void gbar(int bidx) {
    __syncthreads();
    if (threadIdx.x == 0) {
        __threadfence();
        atomicAdd(&d_barCnt, 1);
        int target = bidx * GRID_LOOP;
        int v;
        do {
            asm volatile("ld.global.cg.b32 %0, [%1];" : "=r"(v) : "l"(&d_barCnt));
            if (v < target) __nanosleep(64);
        } while (v < target);
        __threadfence();
    }
    __syncthreads();
}

// ---------------- setup kernels ----------------
__global__ void k_init() {
    int i = blockIdx.x * blockDim.x + threadIdx.x;
    if (i < NN * NH) { d_c[i] = 0.f; d_hsbuf[0][i] = __float2half_rn(0.f); }
    if (i < NN)      { d_deg[i] = 1; d_fill[i] = 0; }
    if (i == 0)      d_barCnt = 0;
}

__global__ void k_deg(const int* __restrict__ dst, int E) {
    int i = blockIdx.x * blockDim.x + threadIdx.x;
    if (i < E) atomicAdd(&d_deg[dst[i]], 1);
}

// scan (CSR offsets) + dinv in one kernel
__global__ void k_scan(int E) {
    __shared__ int ssum[1024];
    int tid = threadIdx.x;
    int loc[10]; int run = 0;
#pragma unroll
    for (int i = 0; i < 10; i++) {
        int v = tid * 10 + i;
        int c = (v < NN) ? (d_deg[v] - 1) : 0;
        loc[i] = run; run += c;
    }
    ssum[tid] = run; __syncthreads();
    for (int off = 1; off < 1024; off <<= 1) {
        int t = (tid >= off) ? ssum[tid - off] : 0;
        __syncthreads();
        ssum[tid] += t;
        __syncthreads();
    }
    int base = (tid == 0) ? 0 : ssum[tid - 1];
#pragma unroll
    for (int i = 0; i < 10; i++) {
        int v = tid * 10 + i;
        if (v < NN) {
            d_off[v] = base + loc[i];
            d_dinv[v] = rsqrtf((float)d_deg[v]);
        }
    }
    if (tid == 0) d_off[NN] = E;
}

__global__ void k_fill(const int* __restrict__ src, const int* __restrict__ dst, int E) {
    int i = blockIdx.x * blockDim.x + threadIdx.x;
    if (i < E) {
        int v = dst[i];
        int p = d_off[v] + atomicAdd(&d_fill[v], 1);
        d_adj[p] = src[i];
    }
}

// convert x to fp16 once (halves the Px gather traffic)
__global__ void k_xconv(const float* __restrict__ x) {
    size_t i = ((size_t)blockIdx.x * 256 + threadIdx.x) * 2;
    float2 v = *(const float2*)&x[i];
    *(__half2*)&d_xh[i] = __floats2half2_rn(v.x, v.y);
}

// fused: blocks < PX_BLOCKS compute Px from fp16 x (fp16 hi/lo split of the fp32 sum);
// tail blocks pack weights
#define WPK_N   196608
#define BPK_END (WPK_N + 512)
#define W1P_END (BPK_END + NH * 256)
#define WCP_END (W1P_END + NH * NOUT)
__global__ void k_pxpack(const float* __restrict__ Wi, const float* __restrict__ bi,
                         const float* __restrict__ Wf, const float* __restrict__ bf,
                         const float* __restrict__ Wo, const float* __restrict__ bo,
                         const float* __restrict__ Wg, const float* __restrict__ bg,
                         const float* __restrict__ W1, const float* __restrict__ Wc) {
    if (blockIdx.x < PX_BLOCKS) {
        int w = blockIdx.x * 8 + (threadIdx.x >> 5);
        int t = w / NN, v = w - t * NN;
        int l2 = (threadIdx.x & 31) * 2;
        const __half* xt = d_xh + (size_t)t * NN * NIN;
        float2 a = make_float2(0.f, 0.f);
        int e = d_off[v], end = d_off[v + 1];
#pragma unroll 4
        for (; e < end; e++) {
            int s = d_adj[e];
            float ds = d_dinv[s];
            float2 xv = h2f2(*(const uint32_t*)&xt[s * NIN + l2]);
            a.x += ds * xv.x; a.y += ds * xv.y;
        }
        float dv = d_dinv[v];
        float2 xs = h2f2(*(const uint32_t*)&xt[v * NIN + l2]);
        a.x = dv * (a.x + dv * xs.x);
        a.y = dv * (a.y + dv * xs.y);
        __half h0 = __float2half_rn(a.x), h1 = __float2half_rn(a.y);
        __half l0 = __float2half_rn(a.x - __half2float(h0));
        __half l1 = __float2half_rn(a.y - __half2float(h1));
        size_t o = ((size_t)t * NN + v) * NIN + l2;
        *(uint32_t*)&d_Pxh[o] = pkh(h0, h1);
        *(uint32_t*)&d_Pxl[o] = pkh(l0, l1);
    } else {
        int idx = (blockIdx.x - PX_BLOCKS) * 256 + threadIdx.x;
        if (idx < WPK_N) {
            int s = idx / 98304;
            int r = idx % 98304;
            int c = r / 32768;
            int r2 = r % 32768;
            int n = r2 >> 6, kk = r2 & 63;
            int j = n >> 2, g = n & 3, k = c * 64 + kk;
            const float* W = (g == 0) ? Wi : (g == 1) ? Wf : (g == 2) ? Wo : Wg;
            float w = W[j * KTOT + k];
            __half hi = __float2half_rn(w);
            d_Wpk[idx] = (s == 0) ? hi : __float2half_rn(w - __half2float(hi));
        } else if (idx < BPK_END) {
            int i = idx - WPK_N;
            int j = i >> 2, g = i & 3;
            const float* b = (g == 0) ? bi : (g == 1) ? bf : (g == 2) ? bo : bg;
            d_bpk[i] = b[j];
        } else if (idx < W1P_END) {
            int r = idx - BPK_END;
            int k = r / 256, cc = r % 256;
            d_W1p[r] = W1[(cc & 127) * 256 + (cc >> 7) * 128 + k];
        } else if (idx < WCP_END) {
            int r = idx - W1P_END;
            int k = r / NOUT, j = r % NOUT;
            d_Wcp[r] = Wc[j * NH + k];
        }
    }
}

// ---------------- persistent loop kernel --------------------------------------
// One stage per K chunk c (0..2): {Ah 8K, Al 8K, Bh 16K, Bl 16K} loaded once;
// all 3 split passes (Ah*Bh, Al*Bh, Ah*Bl) run from this stage.
__device__ __forceinline__ void loadStage(uint32_t sbse, int buf, int c, int t,
                                          int m0, int n0, int tid) {
    uint32_t Ab = sbse + buf * STAGE_BYTES;
    // A: hi + lo, 1024 x cp16
#pragma unroll
    for (int rep = 0; rep < 4; rep++) {
        int q = tid + rep * 256;
        int s = q >> 9, r = q & 511;
        int row = r >> 3, kg = r & 7;
        uint32_t ok = (m0 + row < NN) ? 16 : 0;
        uint32_t dst = Ab + s * 8192 + row * 128 + ((kg ^ (row & 7)) << 4);
        if (c == 0) {
            const __half* src = (s ? d_Pxl : d_Pxh)
                + ((size_t)t * NN + (m0 + row)) * 64 + kg * 8;
            cp16(dst, src, ok);       // Px immutable: L1-cacheable
        } else {
            const __half* src = (s ? d_Phl : d_Phh)
                + (size_t)(m0 + row) * 128 + (c - 1) * 64 + kg * 8;
            cp16cg(dst, src, ok);     // Ph changes every step: bypass L1
        }
    }
    // B: hi + lo, 2048 x cp16
#pragma unroll
    for (int rep = 0; rep < 8; rep++) {
        int q = tid + rep * 256;
        int s = q >> 10, r = q & 1023;
        int nr = r >> 3, kg = r & 7;
        uint32_t dst = Ab + 16384 + s * 16384 + nr * 128 + ((kg ^ (nr & 7)) << 4);
        const __half* src = d_Wpk + (size_t)((s * 3 + c) * 512 + n0 + nr) * 64 + kg * 8;
        cp16(dst, src, 16);
    }
}

__device__ __forceinline__ void gg_chunk(uint32_t Ab, float (&acc)[2][4][4],
                                         int wm, int wn, int g, int lr) {
#pragma unroll
    for (int ks = 0; ks < 4; ks++) {
        uint32_t afh[2][4], afl[2][4], bfh[2][4], bfl[2][4];
#pragma unroll
        for (int mt = 0; mt < 2; mt++) {
            int ar = wm + mt * 16 + (g & 1) * 8 + lr;
            int akg = ks * 2 + (g >> 1);
            uint32_t off = ar * 128 + ((akg ^ (ar & 7)) << 4);
            ldsm4(afh[mt], Ab + off);
            ldsm4(afl[mt], Ab + 8192 + off);
        }
#pragma unroll
        for (int ns2 = 0; ns2 < 2; ns2++) {
            int br = wn + ns2 * 16 + (g >> 1) * 8 + lr;
            int bkg = ks * 2 + (g & 1);
            uint32_t off = br * 128 + ((bkg ^ (br & 7)) << 4);
            ldsm4(bfh[ns2], Ab + 16384 + off);
            ldsm4(bfl[ns2], Ab + 32768 + off);
        }
#pragma unroll
        for (int mt = 0; mt < 2; mt++)
#pragma unroll
            for (int nt = 0; nt < 4; nt++) {
                mma16816(acc[mt][nt], afh[mt], &bfh[nt >> 1][(nt & 1) * 2]);
                mma16816(acc[mt][nt], afl[mt], &bfh[nt >> 1][(nt & 1) * 2]);
                mma16816(acc[mt][nt], afh[mt], &bfl[nt >> 1][(nt & 1) * 2]);
            }
    }
}

__global__ void __launch_bounds__(256, 2) k_loop() {
    extern __shared__ char smem[];
    const uint32_t sbse = smem_u32(smem);
    const int tid = threadIdx.x, lane = tid & 31, w = tid >> 5;
    const int cta = blockIdx.x;
    const int g = lane >> 3, lr = lane & 7;
    const int wm = (w >> 2) * 32, wn = (w & 3) * 32;
    int bseq = 0;

    for (int t = 0; t < TT; t++) {
        const __half* hsr = d_hsbuf[t & 1];
        __half* hsw = d_hsbuf[(t & 1) ^ 1];

        // prefetch first tile's chunk-0 stage: Px + B, both valid pre-barrier
        loadStage(sbse, 0, 0, t, (cta >> 2) * 64, (cta & 3) * 128, tid);
        cp_commit();

        if (t > 0) {
            // ---- prop phase: full-chip parallel fp16 gather, fp32 accumulate ----
            for (int rl = w; rl < ROWS_PER_CTA; rl += 8) {
                int m = cta * ROWS_PER_CTA + rl;
                if (m < NN) {
                    int f4 = lane * 4;
                    uint2 raw = __ldcg((const uint2*)&hsr[m * NH + f4]);
                    float2 s0f = h2f2(raw.x), s1f = h2f2(raw.y);
                    float4 a = make_float4(s0f.x, s0f.y, s1f.x, s1f.y);
                    int e = d_off[m], end = d_off[m + 1];
                    for (; e + 1 < end; e += 2) {
                        int n0i = d_adj[e], n1i = d_adj[e + 1];
                        uint2 r0 = __ldcg((const uint2*)&hsr[n0i * NH + f4]);
                        uint2 r1 = __ldcg((const uint2*)&hsr[n1i * NH + f4]);
                        float2 a0 = h2f2(r0.x), b0 = h2f2(r0.y);
                        float2 a1 = h2f2(r1.x), b1 = h2f2(r1.y);
                        a.x += a0.x + a1.x; a.y += a0.y + a1.y;
                        a.z += b0.x + b1.x; a.w += b0.y + b1.y;
                    }
                    if (e < end) {
                        int n0i = d_adj[e];
                        uint2 r0 = __ldcg((const uint2*)&hsr[n0i * NH + f4]);
                        float2 a0 = h2f2(r0.x), b0 = h2f2(r0.y);
                        a.x += a0.x; a.y += a0.y; a.z += b0.x; a.w += b0.y;
                    }
                    float dv = d_dinv[m];
                    a.x *= dv; a.y *= dv; a.z *= dv; a.w *= dv;
                    __half h0 = __float2half_rn(a.x), h1 = __float2half_rn(a.y);
                    __half h2 = __float2half_rn(a.z), h3 = __float2half_rn(a.w);
                    __half l0 = __float2half_rn(a.x - __half2float(h0));
                    __half l1 = __float2half_rn(a.y - __half2float(h1));
                    __half l2 = __float2half_rn(a.z - __half2float(h2));
                    __half l3 = __float2half_rn(a.w - __half2float(h3));
                    *(uint2*)&d_Phh[m * NH + f4] = make_uint2(pkh(h0, h1), pkh(h2, h3));
                    *(uint2*)&d_Phl[m * NH + f4] = make_uint2(pkh(l0, l1), pkh(l2, l3));
                }
            }
            gbar(++bseq);
        }

        // ---- GEMM + LSTM phase ----
        bool pre = true;
        for (int tile = cta; tile < NTILES; tile += GRID_LOOP) {
            int m0 = (tile >> 2) * 64;
            int n0 = (tile & 3) * 128;

            float acc[2][4][4];
#pragma unroll
            for (int i = 0; i < 2; i++)
#pragma unroll
                for (int j = 0; j < 4; j++)
#pragma unroll
                    for (int q = 0; q < 4; q++) acc[i][j][q] = 0.f;

            if (t == 0) {
                // Ph == 0: only chunk 0 contributes
                if (!pre) { loadStage(sbse, 0, 0, t, m0, n0, tid); cp_commit(); }
                pre = false;
                cp_wait0();
                __syncthreads();
                gg_chunk(sbse, acc, wm, wn, g, lr);
                __syncthreads();
            } else {
                if (!pre) { loadStage(sbse, 0, 0, t, m0, n0, tid); cp_commit(); }
                pre = false;
                loadStage(sbse, 1, 1, t, m0, n0, tid); cp_commit();
#pragma unroll
                for (int c = 0; c < 3; c++) {
                    if (c < 2) cp_wait1(); else cp_wait0();
                    __syncthreads();
                    gg_chunk(sbse + (c & 1) * STAGE_BYTES, acc, wm, wn, g, lr);
                    __syncthreads();
                    if (c == 0) { loadStage(sbse, 0, 2, t, m0, n0, tid); cp_commit(); }
                }
            }

            // stage accumulators to smem [64][132] (reuses stage buffer 0)
            float* Cs = (float*)smem;
#pragma unroll
            for (int mt = 0; mt < 2; mt++)
#pragma unroll
                for (int nt = 0; nt < 4; nt++) {
                    int r = wm + mt * 16 + (lane >> 2);
                    int col = wn + nt * 8 + (lane & 3) * 2;
                    *(float2*)&Cs[r * 132 + col] =
                        make_float2(acc[mt][nt][0], acc[mt][nt][1]);
                    *(float2*)&Cs[(r + 8) * 132 + col] =
                        make_float2(acc[mt][nt][2], acc[mt][nt][3]);
                }
            __syncthreads();

            // fused LSTM epilogue: 64 rows x 32 j's
#pragma unroll
            for (int it = 0; it < 8; it++) {
                int idx = it * 256 + tid;
                int mloc = idx >> 5, jloc = idx & 31;
                int m = m0 + mloc;
                if (m < NN) {
                    float4 prev = *(const float4*)&Cs[mloc * 132 + jloc * 4];
                    int j = (n0 >> 2) + jloc;
                    float4 bb = *(const float4*)&d_bpk[j * 4];
                    float i_ = sigf(prev.x + bb.x);
                    float f_ = sigf(prev.y + bb.y);
                    float o_ = sigf(prev.z + bb.z);
                    float gg = tanhf(prev.w + bb.w);
                    int ci = m * NH + j;
                    float cn = f_ * d_c[ci] + i_ * gg;   // c is CTA-local (fixed map)
                    float hh = o_ * tanhf(cn);
                    d_c[ci] = cn;
                    hsw[ci] = __float2half_rn(d_dinv[m] * hh);
                    if (t == TT - 1) d_h[ci] = hh;
                }
            }
            __syncthreads();
        }
        gbar(++bseq);
    }
}

// ---------------- decoder ----------------
__global__ void k_gemm(int sel, const float* __restrict__ bias, float* __restrict__ Cout,
                       int M, int K, int N) {
    __shared__ __align__(16) float As[16][64];
    __shared__ __align__(16) float Bs[16][64];
    const float* A = sel ? d_Pn  : d_h;
    const float* B = sel ? d_Wcp : d_W1p;
    float*       C = sel ? Cout  : d_HaHb;
    int tid = threadIdx.x;
    int tx = tid & 15, ty = tid >> 4;
    int m0 = blockIdx.x * 64, n0 = blockIdx.y * 64;
    float acc[4][4] = {};
    int lrow = tid >> 2, lkp = (tid & 3) * 4;
    int bk = tid >> 4, bcc = (tid & 15) * 4;
    for (int kc = 0; kc < K; kc += 16) {
        float4 av = make_float4(0.f, 0.f, 0.f, 0.f);
        int grow = m0 + lrow;
        if (grow < M) av = *(const float4*)&A[grow * K + kc + lkp];
        As[lkp + 0][lrow] = av.x; As[lkp + 1][lrow] = av.y;
        As[lkp + 2][lrow] = av.z; As[lkp + 3][lrow] = av.w;
        float4 bv = *(const float4*)&B[(kc + bk) * N + n0 + bcc];
        *(float4*)&Bs[bk][bcc] = bv;
        __syncthreads();
#pragma unroll
        for (int k = 0; k < 16; k++) {
            float4 a = *(const float4*)&As[k][ty * 4];
            float4 b = *(const float4*)&Bs[k][tx * 4];
            float ar[4] = {a.x, a.y, a.z, a.w};
            float br[4] = {b.x, b.y, b.z, b.w};
#pragma unroll
            for (int i = 0; i < 4; i++)
#pragma unroll
                for (int j = 0; j < 4; j++) acc[i][j] = fmaf(ar[i], br[j], acc[i][j]);
        }
        __syncthreads();
    }
    float4 bb = make_float4(0.f, 0.f, 0.f, 0.f);
    if (bias) bb = *(const float4*)&bias[n0 + tx * 4];
#pragma unroll
    for (int i = 0; i < 4; i++) {
        int m = m0 + ty * 4 + i;
        if (m >= M) continue;
        float4 o = make_float4(acc[i][0] + bb.x, acc[i][1] + bb.y,
                               acc[i][2] + bb.z, acc[i][3] + bb.w);
        *(float4*)&C[m * N + n0 + tx * 4] = o;
    }
}

__global__ void k_edge_nodes(const float* __restrict__ b1) {
    int w = blockIdx.x * 8 + (threadIdx.x >> 5);
    if (w >= NN) return;
    int l4 = (threadIdx.x & 31) * 4;
    float4 ha = *(const float4*)&d_HaHb[w * 256 + l4];
    float4 bb = *(const float4*)&b1[l4];
    ha.x += bb.x; ha.y += bb.y; ha.z += bb.z; ha.w += bb.w;
    float4 acc = make_float4(0.f, 0.f, 0.f, 0.f);
    int e = d_off[w], end = d_off[w + 1];
#pragma unroll 2
    for (; e < end; e++) {
        int s = d_adj[e];
        float4 hb = *(const float4*)&d_HaHb[s * 256 + 128 + l4];
        acc.x += fmaxf(ha.x + hb.x, 0.f);
        acc.y += fmaxf(ha.y + hb.y, 0.f);
        acc.z += fmaxf(ha.z + hb.z, 0.f);
        acc.w += fmaxf(ha.w + hb.w, 0.f);
    }
    *(float4*)&d_nodes[w * NH + l4] = acc;
}

__global__ void k_prop2() {
    int w = blockIdx.x * 8 + (threadIdx.x >> 5);
    if (w >= NN) return;
    int l4 = (threadIdx.x & 31) * 4;
    float dv = d_dinv[w];
    float4 sv = *(const float4*)&d_nodes[w * NH + l4];
    float4 acc = make_float4(dv * sv.x, dv * sv.y, dv * sv.z, dv * sv.w);
    int e = d_off[w], end = d_off[w + 1];
#pragma unroll 2
    for (; e < end; e++) {
        int s = d_adj[e];
        float ds = d_dinv[s];
        float4 v0 = *(const float4*)&d_nodes[s * NH + l4];
        acc.x += ds * v0.x; acc.y += ds * v0.y;
        acc.z += ds * v0.z; acc.w += ds * v0.w;
    }
    acc.x *= dv; acc.y *= dv; acc.z *= dv; acc.w *= dv;
    *(float4*)&d_Pn[w * NH + l4] = acc;
}

// ---------------- host launcher ----------------
extern "C" void kernel_launch(void* const* d_in, const int* in_sizes, int n_in,
                              void* d_out, int out_size) {
    const float* x  = (const float*)d_in[0];
    const int*   ei = (const int*)d_in[1];
    const int    E  = in_sizes[2];
    const int* src = ei;
    const int* dst = ei + E;
    const float* Wi = (const float*)d_in[4];
    const float* bi = (const float*)d_in[5];
    const float* Wf = (const float*)d_in[6];
    const float* bf = (const float*)d_in[7];
    const float* Wo = (const float*)d_in[8];
    const float* bo = (const float*)d_in[9];
    const float* Wg = (const float*)d_in[10];
    const float* bg = (const float*)d_in[11];
    const float* W1 = (const float*)d_in[12];
    const float* b1 = (const float*)d_in[13];
    const float* Wc = (const float*)d_in[14];
    const float* bc = (const float*)d_in[15];
    float* out = (float*)d_out;

    static int smem_set = 0;
    if (!smem_set) {
        cudaFuncSetAttribute(k_loop, cudaFuncAttributeMaxDynamicSharedMemorySize,
                             LOOP_SMEM);
        smem_set = 1;
    }

    int packBlocks = (WCP_END + 255) / 256;
    k_init<<<(NN * NH + 255) / 256, 256>>>();
    k_deg<<<(E + 255) / 256, 256>>>(dst, E);
    k_scan<<<1, 1024>>>(E);
    k_fill<<<(E + 255) / 256, 256>>>(src, dst, E);
    k_xconv<<<XC_BLOCKS, 256>>>(x);
    k_pxpack<<<PX_BLOCKS + packBlocks, 256>>>(Wi, bi, Wf, bf, Wo, bo, Wg, bg, W1, Wc);

    k_loop<<<GRID_LOOP, 256, LOOP_SMEM>>>();

    k_gemm<<<dim3((NN + 63) / 64, 4), 256>>>(0, nullptr, nullptr, NN, NH, 256);
    k_edge_nodes<<<NN / 8, 256>>>(b1);
    k_prop2<<<NN / 8, 256>>>();
    k_gemm<<<dim3((NN + 63) / 64, 1), 256>>>(1, bc, out, NN, NH, NOUT);
}

// round 15
// speedup vs baseline: 1.2184x; 1.0402x over previous
#include <cuda_runtime.h>
#include <cuda_fp16.h>
#include <cstdint>

#define NN   10000
#define TT   64
#define NIN  64
#define NH   128
#define NOUT 64
#define KTOT 192
#define EMAX 160000
#define GRID_LOOP 296          // 2 CTAs/SM, co-resident for the global barrier
#define ROWS_PER_CTA 34        // ceil(10000/296)
#define NTILES 628             // 157 m-tiles (BM=64) x 4 n-tiles (BN=128)
#define STAGE_BYTES 49152      // Ah 8K | Al 8K | Bh 16K | Bl 16K
#define LOOP_SMEM 98304        // 2 stage buffers; epilogue reuses buffer 0
#define XC_BLOCKS 80000        // TT*NN*NIN/2/256

// ---------------- device scratch ----------------
__device__ float d_dinv[NN];
__device__ int   d_deg[NN];
__device__ int   d_off[NN + 1];
__device__ int   d_fill[NN];
__device__ int   d_adj[EMAX];
__device__ int   d_barCnt;
__device__ __half d_xh[(size_t)TT * NN * NIN];   // pre-scaled fp16 x (dinv*x)
__device__ __half d_Pxth[NN * NIN];              // per-step Px hi split
__device__ __half d_Pxtl[NN * NIN];              // per-step Px lo split
__device__ __half d_Phh[NN * NH];
__device__ __half d_Phl[NN * NH];
__device__ float d_h[NN * NH];
__device__ float d_c[NN * NH];
__device__ __half d_hsbuf[2][NN * NH];           // fp16 pre-scaled hidden state
__device__ __half d_Wpk[2 * 3 * 512 * 64];  // [split][chunk64][n=j*4+g][k64]
__device__ float d_bpk[512];                 // [j*4+g]
__device__ float d_W1p[NH * 256];
__device__ float d_Wcp[NH * NOUT];
__device__ float d_HaHb[NN * 256];
__device__ float d_nodes[NN * NH];
__device__ float d_Pn[NN * NH];

// ---------------- helpers ----------------
__device__ __forceinline__ uint32_t smem_u32(const void* p) {
    uint32_t a;
    asm("{ .reg .u64 t; cvta.to.shared.u64 t, %1; cvt.u32.u64 %0, t; }" : "=r"(a) : "l"(p));
    return a;
}
__device__ __forceinline__ uint32_t pkh(__half a, __half b) {
    return (uint32_t)__half_as_ushort(a) | ((uint32_t)__half_as_ushort(b) << 16);
}
__device__ __forceinline__ float2 h2f2(uint32_t u) {
    __half2 h = *reinterpret_cast<__half2*>(&u);
    return __half22float2(h);
}
__device__ __forceinline__ void cp16(uint32_t dst, const void* src, uint32_t srcsize) {
    asm volatile("cp.async.ca.shared.global [%0], [%1], 16, %2;"
                 :: "r"(dst), "l"(src), "r"(srcsize) : "memory");
}
__device__ __forceinline__ void cp16cg(uint32_t dst, const void* src, uint32_t srcsize) {
    asm volatile("cp.async.cg.shared.global [%0], [%1], 16, %2;"
                 :: "r"(dst), "l"(src), "r"(srcsize) : "memory");
}
__device__ __forceinline__ void cp_commit() {
    asm volatile("cp.async.commit_group;" ::: "memory");
}
__device__ __forceinline__ void cp_wait1() {
    asm volatile("cp.async.wait_group 1;" ::: "memory");
}
__device__ __forceinline__ void cp_wait0() {
    asm volatile("cp.async.wait_group 0;" ::: "memory");
}
__device__ __forceinline__ void ldsm4(uint32_t* r, uint32_t addr) {
    asm volatile("ldmatrix.sync.aligned.m8n8.x4.shared.b16 {%0,%1,%2,%3}, [%4];"
                 : "=r"(r[0]), "=r"(r[1]), "=r"(r[2]), "=r"(r[3]) : "r"(addr));
}
__device__ __forceinline__ void mma16816(float* c, const uint32_t* a, const uint32_t* b) {
    asm volatile("mma.sync.aligned.m16n8k16.row.col.f32.f16.f16.f32 "
                 "{%0,%1,%2,%3}, {%4,%5,%6,%7}, {%8,%9}, {%0,%1,%2,%3};"
                 : "+f"(c[0]), "+f"(c[1]), "+f"(c[2]), "+f"(c[3])
                 : "r"(a[0]), "r"(a[1]), "r"(a[2]), "r"(a[3]), "r"(b[0]), "r"(b[1]));
}
__device__ __forceinline__ float sigf(float x) { return 1.0f / (1.0f + __expf(-x)); }

// generation-free global barrier: monotone counter, target = bidx * GRID_LOOP
__device__ __forceinline__ void gbar(int bidx) {
    __syncthreads();
    if (threadIdx.x == 0) {
        __threadfence();
        atomicAdd(&d_barCnt, 1);
        int target = bidx * GRID_LOOP;
        int v;
        do {
            asm volatile("ld.global.cg.b32 %0, [%1];" : "=r"(v) : "l"(&d_barCnt));
            if (v < target) __nanosleep(64);
        } while (v < target);
        __threadfence();
    }
    __syncthreads();
}

// ---------------- setup kernels ----------------
__global__ void k_init() {
    int i = blockIdx.x * blockDim.x + threadIdx.x;
    if (i < NN * NH) { d_c[i] = 0.f; d_hsbuf[0][i] = __float2half_rn(0.f); }
    if (i < NN)      { d_deg[i] = 1; d_fill[i] = 0; }
    if (i == 0)      d_barCnt = 0;
}

__global__ void k_deg(const int* __restrict__ dst, int E) {
    int i = blockIdx.x * blockDim.x + threadIdx.x;
    if (i < E) atomicAdd(&d_deg[dst[i]], 1);
}

// scan (CSR offsets) + dinv in one kernel
__global__ void k_scan(int E) {
    __shared__ int ssum[1024];
    int tid = threadIdx.x;
    int loc[10]; int run = 0;
#pragma unroll
    for (int i = 0; i < 10; i++) {
        int v = tid * 10 + i;
        int c = (v < NN) ? (d_deg[v] - 1) : 0;
        loc[i] = run; run += c;
    }
    ssum[tid] = run; __syncthreads();
    for (int off = 1; off < 1024; off <<= 1) {
        int t = (tid >= off) ? ssum[tid - off] : 0;
        __syncthreads();
        ssum[tid] += t;
        __syncthreads();
    }
    int base = (tid == 0) ? 0 : ssum[tid - 1];
#pragma unroll
    for (int i = 0; i < 10; i++) {
        int v = tid * 10 + i;
        if (v < NN) {
            d_off[v] = base + loc[i];
            d_dinv[v] = rsqrtf((float)d_deg[v]);
        }
    }
    if (tid == 0) d_off[NN] = E;
}

__global__ void k_fill(const int* __restrict__ src, const int* __restrict__ dst, int E) {
    int i = blockIdx.x * blockDim.x + threadIdx.x;
    if (i < E) {
        int v = dst[i];
        int p = d_off[v] + atomicAdd(&d_fill[v], 1);
        d_adj[p] = src[i];
    }
}

// convert x to PRE-SCALED fp16 once: xh[t,v,:] = half(dinv[v] * x[t,v,:])
__global__ void k_xconv(const float* __restrict__ x) {
    size_t i = ((size_t)blockIdx.x * 256 + threadIdx.x) * 2;
    int v = (int)((i >> 6) % NN);
    float dv = d_dinv[v];
    float2 val = *(const float2*)&x[i];
    *(__half2*)&d_xh[i] = __floats2half2_rn(dv * val.x, dv * val.y);
}

// weight packing (fp16 hi/lo split, [j*4+g] column order) + decoder weights
#define WPK_N   196608
#define BPK_END (WPK_N + 512)
#define W1P_END (BPK_END + NH * 256)
#define WCP_END (W1P_END + NH * NOUT)
__global__ void k_pack(const float* __restrict__ Wi, const float* __restrict__ bi,
                       const float* __restrict__ Wf, const float* __restrict__ bf,
                       const float* __restrict__ Wo, const float* __restrict__ bo,
                       const float* __restrict__ Wg, const float* __restrict__ bg,
                       const float* __restrict__ W1, const float* __restrict__ Wc) {
    int idx = blockIdx.x * 256 + threadIdx.x;
    if (idx < WPK_N) {
        int s = idx / 98304;
        int r = idx % 98304;
        int c = r / 32768;
        int r2 = r % 32768;
        int n = r2 >> 6, kk = r2 & 63;
        int j = n >> 2, g = n & 3, k = c * 64 + kk;
        const float* W = (g == 0) ? Wi : (g == 1) ? Wf : (g == 2) ? Wo : Wg;
        float w = W[j * KTOT + k];
        __half hi = __float2half_rn(w);
        d_Wpk[idx] = (s == 0) ? hi : __float2half_rn(w - __half2float(hi));
    } else if (idx < BPK_END) {
        int i = idx - WPK_N;
        int j = i >> 2, g = i & 3;
        const float* b = (g == 0) ? bi : (g == 1) ? bf : (g == 2) ? bo : bg;
        d_bpk[i] = b[j];
    } else if (idx < W1P_END) {
        int r = idx - BPK_END;
        int k = r / 256, cc = r % 256;
        d_W1p[r] = W1[(cc & 127) * 256 + (cc >> 7) * 128 + k];
    } else if (idx < WCP_END) {
        int r = idx - W1P_END;
        int k = r / NOUT, j = r % NOUT;
        d_Wcp[r] = Wc[j * NH + k];
    }
}

// ---------------- persistent loop kernel --------------------------------------
// One stage per K chunk c (0..2): {Ah 8K, Al 8K, Bh 16K, Bl 16K} loaded once;
// all 3 split passes (Ah*Bh, Al*Bh, Ah*Bl) run from this stage.
__device__ __forceinline__ void loadStage(uint32_t sbse, int buf, int c,
                                          int m0, int n0, int tid) {
    uint32_t Ab = sbse + buf * STAGE_BYTES;
    // A: hi + lo, 1024 x cp16 — all step-varying now: bypass L1
#pragma unroll
    for (int rep = 0; rep < 4; rep++) {
        int q = tid + rep * 256;
        int s = q >> 9, r = q & 511;
        int row = r >> 3, kg = r & 7;
        uint32_t ok = (m0 + row < NN) ? 16 : 0;
        uint32_t dst = Ab + s * 8192 + row * 128 + ((kg ^ (row & 7)) << 4);
        const __half* src;
        if (c == 0) src = (s ? d_Pxtl : d_Pxth) + (size_t)(m0 + row) * 64 + kg * 8;
        else        src = (s ? d_Phl : d_Phh) + (size_t)(m0 + row) * 128 + (c - 1) * 64 + kg * 8;
        cp16cg(dst, src, ok);
    }
    // B: hi + lo, 2048 x cp16 — immutable: L1-cacheable
#pragma unroll
    for (int rep = 0; rep < 8; rep++) {
        int q = tid + rep * 256;
        int s = q >> 10, r = q & 1023;
        int nr = r >> 3, kg = r & 7;
        uint32_t dst = Ab + 16384 + s * 16384 + nr * 128 + ((kg ^ (nr & 7)) << 4);
        const __half* src = d_Wpk + (size_t)((s * 3 + c) * 512 + n0 + nr) * 64 + kg * 8;
        cp16(dst, src, 16);
    }
}

__global__ void __launch_bounds__(256, 2) k_loop() {
    extern __shared__ char smem[];
    const uint32_t sbse = smem_u32(smem);
    const int tid = threadIdx.x, lane = tid & 31, w = tid >> 5;
    const int cta = blockIdx.x;
    const int g = lane >> 3, lr = lane & 7;
    const int wm = (w >> 2) * 32, wn = (w & 3) * 32;

    for (int t = 0; t < TT; t++) {
        const __half* hsr = d_hsbuf[t & 1];
        __half* hsw = d_hsbuf[(t & 1) ^ 1];
        const __half* xt = d_xh + (size_t)t * NN * NIN;

        // ---- prop phase: combined 192-feature gather (hs 128 + x_t 64) ----
        for (int rl = w; rl < ROWS_PER_CTA; rl += 8) {
            int m = cta * ROWS_PER_CTA + rl;
            if (m < NN) {
                int f4 = lane * 4, f2 = lane * 2;
                uint2 raw = __ldcg((const uint2*)&hsr[m * NH + f4]);
                float2 s0f = h2f2(raw.x), s1f = h2f2(raw.y);
                float4 a = make_float4(s0f.x, s0f.y, s1f.x, s1f.y);
                float2 ax = h2f2(__ldcg((const unsigned int*)&xt[m * NIN + f2]));
                int e = d_off[m], end = d_off[m + 1];
                for (; e + 1 < end; e += 2) {
                    int n0i = d_adj[e], n1i = d_adj[e + 1];
                    uint2 r0 = __ldcg((const uint2*)&hsr[n0i * NH + f4]);
                    uint2 r1 = __ldcg((const uint2*)&hsr[n1i * NH + f4]);
                    unsigned int x0 = __ldcg((const unsigned int*)&xt[n0i * NIN + f2]);
                    unsigned int x1 = __ldcg((const unsigned int*)&xt[n1i * NIN + f2]);
                    float2 a0 = h2f2(r0.x), b0 = h2f2(r0.y);
                    float2 a1 = h2f2(r1.x), b1 = h2f2(r1.y);
                    float2 xa = h2f2(x0), xb = h2f2(x1);
                    a.x += a0.x + a1.x; a.y += a0.y + a1.y;
                    a.z += b0.x + b1.x; a.w += b0.y + b1.y;
                    ax.x += xa.x + xb.x; ax.y += xa.y + xb.y;
                }
                if (e < end) {
                    int n0i = d_adj[e];
                    uint2 r0 = __ldcg((const uint2*)&hsr[n0i * NH + f4]);
                    unsigned int x0 = __ldcg((const unsigned int*)&xt[n0i * NIN + f2]);
                    float2 a0 = h2f2(r0.x), b0 = h2f2(r0.y);
                    float2 xa = h2f2(x0);
                    a.x += a0.x; a.y += a0.y; a.z += b0.x; a.w += b0.y;
                    ax.x += xa.x; ax.y += xa.y;
                }
                float dv = d_dinv[m];
                a.x *= dv; a.y *= dv; a.z *= dv; a.w *= dv;
                ax.x *= dv; ax.y *= dv;
                __half h0 = __float2half_rn(a.x), h1 = __float2half_rn(a.y);
                __half h2 = __float2half_rn(a.z), h3 = __float2half_rn(a.w);
                __half l0 = __float2half_rn(a.x - __half2float(h0));
                __half l1 = __float2half_rn(a.y - __half2float(h1));
                __half l2 = __float2half_rn(a.z - __half2float(h2));
                __half l3 = __float2half_rn(a.w - __half2float(h3));
                *(uint2*)&d_Phh[m * NH + f4] = make_uint2(pkh(h0, h1), pkh(h2, h3));
                *(uint2*)&d_Phl[m * NH + f4] = make_uint2(pkh(l0, l1), pkh(l2, l3));
                __half xh0 = __float2half_rn(ax.x), xh1 = __float2half_rn(ax.y);
                __half xl0 = __float2half_rn(ax.x - __half2float(xh0));
                __half xl1 = __float2half_rn(ax.y - __half2float(xh1));
                *(uint32_t*)&d_Pxth[m * NIN + f2] = pkh(xh0, xh1);
                *(uint32_t*)&d_Pxtl[m * NIN + f2] = pkh(xl0, xl1);
            }
        }
        gbar(2 * t + 1);

        // ---- GEMM + LSTM phase ----
        for (int tile = cta; tile < NTILES; tile += GRID_LOOP) {
            int m0 = (tile >> 2) * 64;
            int n0 = (tile & 3) * 128;

            float acc[2][4][4];
#pragma unroll
            for (int i = 0; i < 2; i++)
#pragma unroll
                for (int j = 0; j < 4; j++)
#pragma unroll
                    for (int q = 0; q < 4; q++) acc[i][j][q] = 0.f;

            loadStage(sbse, 0, 0, m0, n0, tid); cp_commit();
            loadStage(sbse, 1, 1, m0, n0, tid); cp_commit();

#pragma unroll
            for (int c = 0; c < 3; c++) {
                if (c < 2) cp_wait1(); else cp_wait0();
                __syncthreads();
                uint32_t Ab = sbse + (c & 1) * STAGE_BYTES;
#pragma unroll
                for (int ks = 0; ks < 4; ks++) {
                    uint32_t afh[2][4], afl[2][4], bfh[2][4], bfl[2][4];
#pragma unroll
                    for (int mt = 0; mt < 2; mt++) {
                        int ar = wm + mt * 16 + (g & 1) * 8 + lr;
                        int akg = ks * 2 + (g >> 1);
                        uint32_t off = ar * 128 + ((akg ^ (ar & 7)) << 4);
                        ldsm4(afh[mt], Ab + off);
                        ldsm4(afl[mt], Ab + 8192 + off);
                    }
#pragma unroll
                    for (int ns2 = 0; ns2 < 2; ns2++) {
                        int br = wn + ns2 * 16 + (g >> 1) * 8 + lr;
                        int bkg = ks * 2 + (g & 1);
                        uint32_t off = br * 128 + ((bkg ^ (br & 7)) << 4);
                        ldsm4(bfh[ns2], Ab + 16384 + off);
                        ldsm4(bfl[ns2], Ab + 32768 + off);
                    }
#pragma unroll
                    for (int mt = 0; mt < 2; mt++)
#pragma unroll
                        for (int nt = 0; nt < 4; nt++) {
                            mma16816(acc[mt][nt], afh[mt], &bfh[nt >> 1][(nt & 1) * 2]);
                            mma16816(acc[mt][nt], afl[mt], &bfh[nt >> 1][(nt & 1) * 2]);
                            mma16816(acc[mt][nt], afh[mt], &bfl[nt >> 1][(nt & 1) * 2]);
                        }
                }
                __syncthreads();
                if (c == 0) { loadStage(sbse, 0, 2, m0, n0, tid); cp_commit(); }
            }

            // stage accumulators to smem [64][132] (reuses stage buffer 0)
            float* Cs = (float*)smem;
#pragma unroll
            for (int mt = 0; mt < 2; mt++)
#pragma unroll
                for (int nt = 0; nt < 4; nt++) {
                    int r = wm + mt * 16 + (lane >> 2);
                    int col = wn + nt * 8 + (lane & 3) * 2;
                    *(float2*)&Cs[r * 132 + col] =
                        make_float2(acc[mt][nt][0], acc[mt][nt][1]);
                    *(float2*)&Cs[(r + 8) * 132 + col] =
                        make_float2(acc[mt][nt][2], acc[mt][nt][3]);
                }
            __syncthreads();

            // fused LSTM epilogue: 64 rows x 32 j's
#pragma unroll
            for (int it = 0; it < 8; it++) {
                int idx = it * 256 + tid;
                int mloc = idx >> 5, jloc = idx & 31;
                int m = m0 + mloc;
                if (m < NN) {
                    float4 pre = *(const float4*)&Cs[mloc * 132 + jloc * 4];
                    int j = (n0 >> 2) + jloc;
                    float4 bb = *(const float4*)&d_bpk[j * 4];
                    float i_ = sigf(pre.x + bb.x);
                    float f_ = sigf(pre.y + bb.y);
                    float o_ = sigf(pre.z + bb.z);
                    float gg = tanhf(pre.w + bb.w);
                    int ci = m * NH + j;
                    float cn = f_ * d_c[ci] + i_ * gg;   // c is CTA-local (fixed map)
                    float hh = o_ * tanhf(cn);
                    d_c[ci] = cn;
                    hsw[ci] = __float2half_rn(d_dinv[m] * hh);
                    if (t == TT - 1) d_h[ci] = hh;
                }
            }
            __syncthreads();
        }
        gbar(2 * t + 2);
    }
}

// ---------------- decoder ----------------
__global__ void k_gemm(int sel, const float* __restrict__ bias, float* __restrict__ Cout,
                       int M, int K, int N) {
    __shared__ __align__(16) float As[16][64];
    __shared__ __align__(16) float Bs[16][64];
    const float* A = sel ? d_Pn  : d_h;
    const float* B = sel ? d_Wcp : d_W1p;
    float*       C = sel ? Cout  : d_HaHb;
    int tid = threadIdx.x;
    int tx = tid & 15, ty = tid >> 4;
    int m0 = blockIdx.x * 64, n0 = blockIdx.y * 64;
    float acc[4][4] = {};
    int lrow = tid >> 2, lkp = (tid & 3) * 4;
    int bk = tid >> 4, bcc = (tid & 15) * 4;
    for (int kc = 0; kc < K; kc += 16) {
        float4 av = make_float4(0.f, 0.f, 0.f, 0.f);
        int grow = m0 + lrow;
        if (grow < M) av = *(const float4*)&A[grow * K + kc + lkp];
        As[lkp + 0][lrow] = av.x; As[lkp + 1][lrow] = av.y;
        As[lkp + 2][lrow] = av.z; As[lkp + 3][lrow] = av.w;
        float4 bv = *(const float4*)&B[(kc + bk) * N + n0 + bcc];
        *(float4*)&Bs[bk][bcc] = bv;
        __syncthreads();
#pragma unroll
        for (int k = 0; k < 16; k++) {
            float4 a = *(const float4*)&As[k][ty * 4];
            float4 b = *(const float4*)&Bs[k][tx * 4];
            float ar[4] = {a.x, a.y, a.z, a.w};
            float br[4] = {b.x, b.y, b.z, b.w};
#pragma unroll
            for (int i = 0; i < 4; i++)
#pragma unroll
                for (int j = 0; j < 4; j++) acc[i][j] = fmaf(ar[i], br[j], acc[i][j]);
        }
        __syncthreads();
    }
    float4 bb = make_float4(0.f, 0.f, 0.f, 0.f);
    if (bias) bb = *(const float4*)&bias[n0 + tx * 4];
#pragma unroll
    for (int i = 0; i < 4; i++) {
        int m = m0 + ty * 4 + i;
        if (m >= M) continue;
        float4 o = make_float4(acc[i][0] + bb.x, acc[i][1] + bb.y,
                               acc[i][2] + bb.z, acc[i][3] + bb.w);
        *(float4*)&C[m * N + n0 + tx * 4] = o;
    }
}

__global__ void k_edge_nodes(const float* __restrict__ b1) {
    int w = blockIdx.x * 8 + (threadIdx.x >> 5);
    if (w >= NN) return;
    int l4 = (threadIdx.x & 31) * 4;
    float4 ha = *(const float4*)&d_HaHb[w * 256 + l4];
    float4 bb = *(const float4*)&b1[l4];
    ha.x += bb.x; ha.y += bb.y; ha.z += bb.z; ha.w += bb.w;
    float4 acc = make_float4(0.f, 0.f, 0.f, 0.f);
    int e = d_off[w], end = d_off[w + 1];
#pragma unroll 2
    for (; e < end; e++) {
        int s = d_adj[e];
        float4 hb = *(const float4*)&d_HaHb[s * 256 + 128 + l4];
        acc.x += fmaxf(ha.x + hb.x, 0.f);
        acc.y += fmaxf(ha.y + hb.y, 0.f);
        acc.z += fmaxf(ha.z + hb.z, 0.f);
        acc.w += fmaxf(ha.w + hb.w, 0.f);
    }
    *(float4*)&d_nodes[w * NH + l4] = acc;
}

__global__ void k_prop2() {
    int w = blockIdx.x * 8 + (threadIdx.x >> 5);
    if (w >= NN) return;
    int l4 = (threadIdx.x & 31) * 4;
    float dv = d_dinv[w];
    float4 sv = *(const float4*)&d_nodes[w * NH + l4];
    float4 acc = make_float4(dv * sv.x, dv * sv.y, dv * sv.z, dv * sv.w);
    int e = d_off[w], end = d_off[w + 1];
#pragma unroll 2
    for (; e < end; e++) {
        int s = d_adj[e];
        float ds = d_dinv[s];
        float4 v0 = *(const float4*)&d_nodes[s * NH + l4];
        acc.x += ds * v0.x; acc.y += ds * v0.y;
        acc.z += ds * v0.z; acc.w += ds * v0.w;
    }
    acc.x *= dv; acc.y *= dv; acc.z *= dv; acc.w *= dv;
    *(float4*)&d_Pn[w * NH + l4] = acc;
}

// ---------------- host launcher ----------------
extern "C" void kernel_launch(void* const* d_in, const int* in_sizes, int n_in,
                              void* d_out, int out_size) {
    const float* x  = (const float*)d_in[0];
    const int*   ei = (const int*)d_in[1];
    const int    E  = in_sizes[2];
    const int* src = ei;
    const int* dst = ei + E;
    const float* Wi = (const float*)d_in[4];
    const float* bi = (const float*)d_in[5];
    const float* Wf = (const float*)d_in[6];
    const float* bf = (const float*)d_in[7];
    const float* Wo = (const float*)d_in[8];
    const float* bo = (const float*)d_in[9];
    const float* Wg = (const float*)d_in[10];
    const float* bg = (const float*)d_in[11];
    const float* W1 = (const float*)d_in[12];
    const float* b1 = (const float*)d_in[13];
    const float* Wc = (const float*)d_in[14];
    const float* bc = (const float*)d_in[15];
    float* out = (float*)d_out;

    static int smem_set = 0;
    if (!smem_set) {
        cudaFuncSetAttribute(k_loop, cudaFuncAttributeMaxDynamicSharedMemorySize,
                             LOOP_SMEM);
        smem_set = 1;
    }

    int packBlocks = (WCP_END + 255) / 256;
    k_init<<<(NN * NH + 255) / 256, 256>>>();
    k_deg<<<(E + 255) / 256, 256>>>(dst, E);
    k_scan<<<1, 1024>>>(E);
    k_fill<<<(E + 255) / 256, 256>>>(src, dst, E);
    k_xconv<<<XC_BLOCKS, 256>>>(x);
    k_pack<<<packBlocks, 256>>>(Wi, bi, Wf, bf, Wo, bo, Wg, bg, W1, Wc);

    k_loop<<<GRID_LOOP, 256, LOOP_SMEM>>>();

    k_gemm<<<dim3((NN + 63) / 64, 4), 256>>>(0, nullptr, nullptr, NN, NH, 256);
    k_edge_nodes<<<NN / 8, 256>>>(b1);
    k_prop2<<<NN / 8, 256>>>();
    k_gemm<<<dim3((NN + 63) / 64, 1), 256>>>(1, bc, out, NN, NH, NOUT);
}

// round 16
// speedup vs baseline: 1.3810x; 1.1334x over previous
#include <cuda_runtime.h>
#include <cuda_fp16.h>
#include <cstdint>

#define NN   10000
#define TT   64
#define NIN  64
#define NH   128
#define NOUT 64
#define KTOT 192
#define EMAX 160000
#define GRID_LOOP 296          // 2 CTAs/SM, co-resident for the global barrier
#define ROWS_PER_CTA 34        // ceil(10000/296)
#define NTILES 628             // 157 m-tiles (BM=64) x 4 n-tiles (BN=128)
#define STAGE_BYTES 32768      // Ah 8K | Al 8K | Bh 16K
#define LOOP_SMEM 65536        // 2 stage buffers; epilogue reuses buffer 0
#define XC_BLOCKS 80000        // TT*NN*NIN/2/256

// ---------------- device scratch ----------------
__device__ float d_dinv[NN];
__device__ int   d_deg[NN];
__device__ int   d_off[NN + 1];
__device__ int   d_fill[NN];
__device__ int   d_adj[EMAX];
__device__ int   d_barCnt;
__device__ __half d_xh[(size_t)TT * NN * NIN];   // pre-scaled fp16 x (dinv*x)
__device__ __half d_Pxth[NN * NIN];              // per-step Px hi split
__device__ __half d_Pxtl[NN * NIN];              // per-step Px lo split
__device__ __half d_Phh[NN * NH];
__device__ __half d_Phl[NN * NH];
__device__ float d_h[NN * NH];
__device__ float d_c[NN * NH];
__device__ __half d_hsbuf[2][NN * NH];           // fp16 pre-scaled hidden state
__device__ __half d_Wpk[3 * 512 * 64];           // [chunk64][n=j*4+g][k64] (hi only)
__device__ float d_bpk[512];                 // [j*4+g]
__device__ float d_W1p[NH * 256];
__device__ float d_Wcp[NH * NOUT];
__device__ float d_HaHb[NN * 256];
__device__ float d_nodes[NN * NH];
__device__ float d_Pn[NN * NH];

// ---------------- helpers ----------------
__device__ __forceinline__ uint32_t smem_u32(const void* p) {
    uint32_t a;
    asm("{ .reg .u64 t; cvta.to.shared.u64 t, %1; cvt.u32.u64 %0, t; }" : "=r"(a) : "l"(p));
    return a;
}
__device__ __forceinline__ uint32_t pkh(__half a, __half b) {
    return (uint32_t)__half_as_ushort(a) | ((uint32_t)__half_as_ushort(b) << 16);
}
__device__ __forceinline__ float2 h2f2(uint32_t u) {
    __half2 h = *reinterpret_cast<__half2*>(&u);
    return __half22float2(h);
}
__device__ __forceinline__ void cp16(uint32_t dst, const void* src, uint32_t srcsize) {
    asm volatile("cp.async.ca.shared.global [%0], [%1], 16, %2;"
                 :: "r"(dst), "l"(src), "r"(srcsize) : "memory");
}
__device__ __forceinline__ void cp16cg(uint32_t dst, const void* src, uint32_t srcsize) {
    asm volatile("cp.async.cg.shared.global [%0], [%1], 16, %2;"
                 :: "r"(dst), "l"(src), "r"(srcsize) : "memory");
}
__device__ __forceinline__ void cp_commit() {
    asm volatile("cp.async.commit_group;" ::: "memory");
}
__device__ __forceinline__ void cp_wait1() {
    asm volatile("cp.async.wait_group 1;" ::: "memory");
}
__device__ __forceinline__ void cp_wait0() {
    asm volatile("cp.async.wait_group 0;" ::: "memory");
}
__device__ __forceinline__ void ldsm4(uint32_t* r, uint32_t addr) {
    asm volatile("ldmatrix.sync.aligned.m8n8.x4.shared.b16 {%0,%1,%2,%3}, [%4];"
                 : "=r"(r[0]), "=r"(r[1]), "=r"(r[2]), "=r"(r[3]) : "r"(addr));
}
__device__ __forceinline__ void mma16816(float* c, const uint32_t* a, const uint32_t* b) {
    asm volatile("mma.sync.aligned.m16n8k16.row.col.f32.f16.f16.f32 "
                 "{%0,%1,%2,%3}, {%4,%5,%6,%7}, {%8,%9}, {%0,%1,%2,%3};"
                 : "+f"(c[0]), "+f"(c[1]), "+f"(c[2]), "+f"(c[3])
                 : "r"(a[0]), "r"(a[1]), "r"(a[2]), "r"(a[3]), "r"(b[0]), "r"(b[1]));
}
__device__ __forceinline__ float sigf(float x) { return 1.0f / (1.0f + __expf(-x)); }

// generation-free global barrier: monotone counter, target = bidx * GRID_LOOP
__device__ __forceinline__ void gbar(int bidx) {
    __syncthreads();
    if (threadIdx.x == 0) {
        __threadfence();
        atomicAdd(&d_barCnt, 1);
        int target = bidx * GRID_LOOP;
        int v;
        do {
            asm volatile("ld.global.cg.b32 %0, [%1];" : "=r"(v) : "l"(&d_barCnt));
            if (v < target) __nanosleep(64);
        } while (v < target);
        __threadfence();
    }
    __syncthreads();
}

// ---------------- setup kernels ----------------
__global__ void k_init() {
    int i = blockIdx.x * blockDim.x + threadIdx.x;
    if (i < NN * NH) { d_c[i] = 0.f; d_hsbuf[0][i] = __float2half_rn(0.f); }
    if (i < NN)      { d_deg[i] = 1; d_fill[i] = 0; }
    if (i == 0)      d_barCnt = 0;
}

__global__ void k_deg(const int* __restrict__ dst, int E) {
    int i = blockIdx.x * blockDim.x + threadIdx.x;
    if (i < E) atomicAdd(&d_deg[dst[i]], 1);
}

// scan (CSR offsets) + dinv in one kernel
__global__ void k_scan(int E) {
    __shared__ int ssum[1024];
    int tid = threadIdx.x;
    int loc[10]; int run = 0;
#pragma unroll
    for (int i = 0; i < 10; i++) {
        int v = tid * 10 + i;
        int c = (v < NN) ? (d_deg[v] - 1) : 0;
        loc[i] = run; run += c;
    }
    ssum[tid] = run; __syncthreads();
    for (int off = 1; off < 1024; off <<= 1) {
        int t = (tid >= off) ? ssum[tid - off] : 0;
        __syncthreads();
        ssum[tid] += t;
        __syncthreads();
    }
    int base = (tid == 0) ? 0 : ssum[tid - 1];
#pragma unroll
    for (int i = 0; i < 10; i++) {
        int v = tid * 10 + i;
        if (v < NN) {
            d_off[v] = base + loc[i];
            d_dinv[v] = rsqrtf((float)d_deg[v]);
        }
    }
    if (tid == 0) d_off[NN] = E;
}

__global__ void k_fill(const int* __restrict__ src, const int* __restrict__ dst, int E) {
    int i = blockIdx.x * blockDim.x + threadIdx.x;
    if (i < E) {
        int v = dst[i];
        int p = d_off[v] + atomicAdd(&d_fill[v], 1);
        d_adj[p] = src[i];
    }
}

// convert x to PRE-SCALED fp16 once: xh[t,v,:] = half(dinv[v] * x[t,v,:])
__global__ void k_xconv(const float* __restrict__ x) {
    size_t i = ((size_t)blockIdx.x * 256 + threadIdx.x) * 2;
    int v = (int)((i >> 6) % NN);
    float dv = d_dinv[v];
    float2 val = *(const float2*)&x[i];
    *(__half2*)&d_xh[i] = __floats2half2_rn(dv * val.x, dv * val.y);
}

// weight packing (fp16 hi only, [j*4+g] column order) + decoder weights
#define WPK_N   98304
#define BPK_END (WPK_N + 512)
#define W1P_END (BPK_END + NH * 256)
#define WCP_END (W1P_END + NH * NOUT)
__global__ void k_pack(const float* __restrict__ Wi, const float* __restrict__ bi,
                       const float* __restrict__ Wf, const float* __restrict__ bf,
                       const float* __restrict__ Wo, const float* __restrict__ bo,
                       const float* __restrict__ Wg, const float* __restrict__ bg,
                       const float* __restrict__ W1, const float* __restrict__ Wc) {
    int idx = blockIdx.x * 256 + threadIdx.x;
    if (idx < WPK_N) {
        int c = idx / 32768;
        int r2 = idx % 32768;
        int n = r2 >> 6, kk = r2 & 63;
        int j = n >> 2, g = n & 3, k = c * 64 + kk;
        const float* W = (g == 0) ? Wi : (g == 1) ? Wf : (g == 2) ? Wo : Wg;
        d_Wpk[idx] = __float2half_rn(W[j * KTOT + k]);
    } else if (idx < BPK_END) {
        int i = idx - WPK_N;
        int j = i >> 2, g = i & 3;
        const float* b = (g == 0) ? bi : (g == 1) ? bf : (g == 2) ? bo : bg;
        d_bpk[i] = b[j];
    } else if (idx < W1P_END) {
        int r = idx - BPK_END;
        int k = r / 256, cc = r % 256;
        d_W1p[r] = W1[(cc & 127) * 256 + (cc >> 7) * 128 + k];
    } else if (idx < WCP_END) {
        int r = idx - W1P_END;
        int k = r / NOUT, j = r % NOUT;
        d_Wcp[r] = Wc[j * NH + k];
    }
}

// ---------------- persistent loop kernel --------------------------------------
// One stage per K chunk c (0..2): {Ah 8K, Al 8K, Bh 16K} loaded once;
// passes Ah*Bh and Al*Bh run from this stage (weight-lo pass dropped).
__device__ __forceinline__ void loadStage(uint32_t sbse, int buf, int c,
                                          int m0, int n0, int tid) {
    uint32_t Ab = sbse + buf * STAGE_BYTES;
    // A: hi + lo, 1024 x cp16 — step-varying: bypass L1
#pragma unroll
    for (int rep = 0; rep < 4; rep++) {
        int q = tid + rep * 256;
        int s = q >> 9, r = q & 511;
        int row = r >> 3, kg = r & 7;
        uint32_t ok = (m0 + row < NN) ? 16 : 0;
        uint32_t dst = Ab + s * 8192 + row * 128 + ((kg ^ (row & 7)) << 4);
        const __half* src;
        if (c == 0) src = (s ? d_Pxtl : d_Pxth) + (size_t)(m0 + row) * 64 + kg * 8;
        else        src = (s ? d_Phl : d_Phh) + (size_t)(m0 + row) * 128 + (c - 1) * 64 + kg * 8;
        cp16cg(dst, src, ok);
    }
    // B: hi only, 1024 x cp16 — immutable: L1-cacheable
#pragma unroll
    for (int rep = 0; rep < 4; rep++) {
        int q = tid + rep * 256;
        int nr = q >> 3, kg = q & 7;
        uint32_t dst = Ab + 16384 + nr * 128 + ((kg ^ (nr & 7)) << 4);
        const __half* src = d_Wpk + (size_t)(c * 512 + n0 + nr) * 64 + kg * 8;
        cp16(dst, src, 16);
    }
}

__global__ void __launch_bounds__(256, 2) k_loop() {
    extern __shared__ char smem[];
    const uint32_t sbse = smem_u32(smem);
    const int tid = threadIdx.x, lane = tid & 31, w = tid >> 5;
    const int cta = blockIdx.x;
    const int g = lane >> 3, lr = lane & 7;
    const int wm = (w >> 2) * 32, wn = (w & 3) * 32;

    for (int t = 0; t < TT; t++) {
        const __half* hsr = d_hsbuf[t & 1];
        __half* hsw = d_hsbuf[(t & 1) ^ 1];
        const __half* xt = d_xh + (size_t)t * NN * NIN;

        // ---- prop phase: combined 192-feature gather (hs 128 + x_t 64) ----
        for (int rl = w; rl < ROWS_PER_CTA; rl += 8) {
            int m = cta * ROWS_PER_CTA + rl;
            if (m < NN) {
                int f4 = lane * 4, f2 = lane * 2;
                uint2 raw = __ldcg((const uint2*)&hsr[m * NH + f4]);
                float2 s0f = h2f2(raw.x), s1f = h2f2(raw.y);
                float4 a = make_float4(s0f.x, s0f.y, s1f.x, s1f.y);
                float2 ax = h2f2(__ldcg((const unsigned int*)&xt[m * NIN + f2]));
                int e = d_off[m], end = d_off[m + 1];
                for (; e + 1 < end; e += 2) {
                    int n0i = d_adj[e], n1i = d_adj[e + 1];
                    uint2 r0 = __ldcg((const uint2*)&hsr[n0i * NH + f4]);
                    uint2 r1 = __ldcg((const uint2*)&hsr[n1i * NH + f4]);
                    unsigned int x0 = __ldcg((const unsigned int*)&xt[n0i * NIN + f2]);
                    unsigned int x1 = __ldcg((const unsigned int*)&xt[n1i * NIN + f2]);
                    float2 a0 = h2f2(r0.x), b0 = h2f2(r0.y);
                    float2 a1 = h2f2(r1.x), b1 = h2f2(r1.y);
                    float2 xa = h2f2(x0), xb = h2f2(x1);
                    a.x += a0.x + a1.x; a.y += a0.y + a1.y;
                    a.z += b0.x + b1.x; a.w += b0.y + b1.y;
                    ax.x += xa.x + xb.x; ax.y += xa.y + xb.y;
                }
                if (e < end) {
                    int n0i = d_adj[e];
                    uint2 r0 = __ldcg((const uint2*)&hsr[n0i * NH + f4]);
                    unsigned int x0 = __ldcg((const unsigned int*)&xt[n0i * NIN + f2]);
                    float2 a0 = h2f2(r0.x), b0 = h2f2(r0.y);
                    float2 xa = h2f2(x0);
                    a.x += a0.x; a.y += a0.y; a.z += b0.x; a.w += b0.y;
                    ax.x += xa.x; ax.y += xa.y;
                }
                float dv = d_dinv[m];
                a.x *= dv; a.y *= dv; a.z *= dv; a.w *= dv;
                ax.x *= dv; ax.y *= dv;
                __half h0 = __float2half_rn(a.x), h1 = __float2half_rn(a.y);
                __half h2 = __float2half_rn(a.z), h3 = __float2half_rn(a.w);
                __half l0 = __float2half_rn(a.x - __half2float(h0));
                __half l1 = __float2half_rn(a.y - __half2float(h1));
                __half l2 = __float2half_rn(a.z - __half2float(h2));
                __half l3 = __float2half_rn(a.w - __half2float(h3));
                *(uint2*)&d_Phh[m * NH + f4] = make_uint2(pkh(h0, h1), pkh(h2, h3));
                *(uint2*)&d_Phl[m * NH + f4] = make_uint2(pkh(l0, l1), pkh(l2, l3));
                __half xh0 = __float2half_rn(ax.x), xh1 = __float2half_rn(ax.y);
                __half xl0 = __float2half_rn(ax.x - __half2float(xh0));
                __half xl1 = __float2half_rn(ax.y - __half2float(xh1));
                *(uint32_t*)&d_Pxth[m * NIN + f2] = pkh(xh0, xh1);
                *(uint32_t*)&d_Pxtl[m * NIN + f2] = pkh(xl0, xl1);
            }
        }
        gbar(2 * t + 1);

        // ---- GEMM + LSTM phase ----
        for (int tile = cta; tile < NTILES; tile += GRID_LOOP) {
            int m0 = (tile >> 2) * 64;
            int n0 = (tile & 3) * 128;

            float acc[2][4][4];
#pragma unroll
            for (int i = 0; i < 2; i++)
#pragma unroll
                for (int j = 0; j < 4; j++)
#pragma unroll
                    for (int q = 0; q < 4; q++) acc[i][j][q] = 0.f;

            loadStage(sbse, 0, 0, m0, n0, tid); cp_commit();
            loadStage(sbse, 1, 1, m0, n0, tid); cp_commit();

#pragma unroll
            for (int c = 0; c < 3; c++) {
                if (c < 2) cp_wait1(); else cp_wait0();
                __syncthreads();
                uint32_t Ab = sbse + (c & 1) * STAGE_BYTES;
#pragma unroll
                for (int ks = 0; ks < 4; ks++) {
                    uint32_t afh[2][4], afl[2][4], bfh[2][4];
#pragma unroll
                    for (int mt = 0; mt < 2; mt++) {
                        int ar = wm + mt * 16 + (g & 1) * 8 + lr;
                        int akg = ks * 2 + (g >> 1);
                        uint32_t off = ar * 128 + ((akg ^ (ar & 7)) << 4);
                        ldsm4(afh[mt], Ab + off);
                        ldsm4(afl[mt], Ab + 8192 + off);
                    }
#pragma unroll
                    for (int ns2 = 0; ns2 < 2; ns2++) {
                        int br = wn + ns2 * 16 + (g >> 1) * 8 + lr;
                        int bkg = ks * 2 + (g & 1);
                        uint32_t off = br * 128 + ((bkg ^ (br & 7)) << 4);
                        ldsm4(bfh[ns2], Ab + 16384 + off);
                    }
#pragma unroll
                    for (int mt = 0; mt < 2; mt++)
#pragma unroll
                        for (int nt = 0; nt < 4; nt++) {
                            mma16816(acc[mt][nt], afh[mt], &bfh[nt >> 1][(nt & 1) * 2]);
                            mma16816(acc[mt][nt], afl[mt], &bfh[nt >> 1][(nt & 1) * 2]);
                        }
                }
                __syncthreads();
                if (c == 0) { loadStage(sbse, 0, 2, m0, n0, tid); cp_commit(); }
            }

            // stage accumulators to smem [64][132] (reuses stage buffer 0)
            float* Cs = (float*)smem;
#pragma unroll
            for (int mt = 0; mt < 2; mt++)
#pragma unroll
                for (int nt = 0; nt < 4; nt++) {
                    int r = wm + mt * 16 + (lane >> 2);
                    int col = wn + nt * 8 + (lane & 3) * 2;
                    *(float2*)&Cs[r * 132 + col] =
                        make_float2(acc[mt][nt][0], acc[mt][nt][1]);
                    *(float2*)&Cs[(r + 8) * 132 + col] =
                        make_float2(acc[mt][nt][2], acc[mt][nt][3]);
                }
            __syncthreads();

            // fused LSTM epilogue: 64 rows x 32 j's
#pragma unroll
            for (int it = 0; it < 8; it++) {
                int idx = it * 256 + tid;
                int mloc = idx >> 5, jloc = idx & 31;
                int m = m0 + mloc;
                if (m < NN) {
                    float4 pre = *(const float4*)&Cs[mloc * 132 + jloc * 4];
                    int j = (n0 >> 2) + jloc;
                    float4 bb = *(const float4*)&d_bpk[j * 4];
                    float i_ = sigf(pre.x + bb.x);
                    float f_ = sigf(pre.y + bb.y);
                    float o_ = sigf(pre.z + bb.z);
                    float gg = tanhf(pre.w + bb.w);
                    int ci = m * NH + j;
                    float cn = f_ * d_c[ci] + i_ * gg;   // c is CTA-local (fixed map)
                    float hh = o_ * tanhf(cn);
                    d_c[ci] = cn;
                    hsw[ci] = __float2half_rn(d_dinv[m] * hh);
                    if (t == TT - 1) d_h[ci] = hh;
                }
            }
            __syncthreads();
        }
        gbar(2 * t + 2);
    }
}

// ---------------- decoder ----------------
__global__ void k_gemm(int sel, const float* __restrict__ bias, float* __restrict__ Cout,
                       int M, int K, int N) {
    __shared__ __align__(16) float As[16][64];
    __shared__ __align__(16) float Bs[16][64];
    const float* A = sel ? d_Pn  : d_h;
    const float* B = sel ? d_Wcp : d_W1p;
    float*       C = sel ? Cout  : d_HaHb;
    int tid = threadIdx.x;
    int tx = tid & 15, ty = tid >> 4;
    int m0 = blockIdx.x * 64, n0 = blockIdx.y * 64;
    float acc[4][4] = {};
    int lrow = tid >> 2, lkp = (tid & 3) * 4;
    int bk = tid >> 4, bcc = (tid & 15) * 4;
    for (int kc = 0; kc < K; kc += 16) {
        float4 av = make_float4(0.f, 0.f, 0.f, 0.f);
        int grow = m0 + lrow;
        if (grow < M) av = *(const float4*)&A[grow * K + kc + lkp];
        As[lkp + 0][lrow] = av.x; As[lkp + 1][lrow] = av.y;
        As[lkp + 2][lrow] = av.z; As[lkp + 3][lrow] = av.w;
        float4 bv = *(const float4*)&B[(kc + bk) * N + n0 + bcc];
        *(float4*)&Bs[bk][bcc] = bv;
        __syncthreads();
#pragma unroll
        for (int k = 0; k < 16; k++) {
            float4 a = *(const float4*)&As[k][ty * 4];
            float4 b = *(const float4*)&Bs[k][tx * 4];
            float ar[4] = {a.x, a.y, a.z, a.w};
            float br[4] = {b.x, b.y, b.z, b.w};
#pragma unroll
            for (int i = 0; i < 4; i++)
#pragma unroll
                for (int j = 0; j < 4; j++) acc[i][j] = fmaf(ar[i], br[j], acc[i][j]);
        }
        __syncthreads();
    }
    float4 bb = make_float4(0.f, 0.f, 0.f, 0.f);
    if (bias) bb = *(const float4*)&bias[n0 + tx * 4];
#pragma unroll
    for (int i = 0; i < 4; i++) {
        int m = m0 + ty * 4 + i;
        if (m >= M) continue;
        float4 o = make_float4(acc[i][0] + bb.x, acc[i][1] + bb.y,
                               acc[i][2] + bb.z, acc[i][3] + bb.w);
        *(float4*)&C[m * N + n0 + tx * 4] = o;
    }
}

__global__ void k_edge_nodes(const float* __restrict__ b1) {
    int w = blockIdx.x * 8 + (threadIdx.x >> 5);
    if (w >= NN) return;
    int l4 = (threadIdx.x & 31) * 4;
    float4 ha = *(const float4*)&d_HaHb[w * 256 + l4];
    float4 bb = *(const float4*)&b1[l4];
    ha.x += bb.x; ha.y += bb.y; ha.z += bb.z; ha.w += bb.w;
    float4 acc = make_float4(0.f, 0.f, 0.f, 0.f);
    int e = d_off[w], end = d_off[w + 1];
#pragma unroll 2
    for (; e < end; e++) {
        int s = d_adj[e];
        float4 hb = *(const float4*)&d_HaHb[s * 256 + 128 + l4];
        acc.x += fmaxf(ha.x + hb.x, 0.f);
        acc.y += fmaxf(ha.y + hb.y, 0.f);
        acc.z += fmaxf(ha.z + hb.z, 0.f);
        acc.w += fmaxf(ha.w + hb.w, 0.f);
    }
    *(float4*)&d_nodes[w * NH + l4] = acc;
}

__global__ void k_prop2() {
    int w = blockIdx.x * 8 + (threadIdx.x >> 5);
    if (w >= NN) return;
    int l4 = (threadIdx.x & 31) * 4;
    float dv = d_dinv[w];
    float4 sv = *(const float4*)&d_nodes[w * NH + l4];
    float4 acc = make_float4(dv * sv.x, dv * sv.y, dv * sv.z, dv * sv.w);
    int e = d_off[w], end = d_off[w + 1];
#pragma unroll 2
    for (; e < end; e++) {
        int s = d_adj[e];
        float ds = d_dinv[s];
        float4 v0 = *(const float4*)&d_nodes[s * NH + l4];
        acc.x += ds * v0.x; acc.y += ds * v0.y;
        acc.z += ds * v0.z; acc.w += ds * v0.w;
    }
    acc.x *= dv; acc.y *= dv; acc.z *= dv; acc.w *= dv;
    *(float4*)&d_Pn[w * NH + l4] = acc;
}

// ---------------- host launcher ----------------
extern "C" void kernel_launch(void* const* d_in, const int* in_sizes, int n_in,
                              void* d_out, int out_size) {
    const float* x  = (const float*)d_in[0];
    const int*   ei = (const int*)d_in[1];
    const int    E  = in_sizes[2];
    const int* src = ei;
    const int* dst = ei + E;
    const float* Wi = (const float*)d_in[4];
    const float* bi = (const float*)d_in[5];
    const float* Wf = (const float*)d_in[6];
    const float* bf = (const float*)d_in[7];
    const float* Wo = (const float*)d_in[8];
    const float* bo = (const float*)d_in[9];
    const float* Wg = (const float*)d_in[10];
    const float* bg = (const float*)d_in[11];
    const float* W1 = (const float*)d_in[12];
    const float* b1 = (const float*)d_in[13];
    const float* Wc = (const float*)d_in[14];
    const float* bc = (const float*)d_in[15];
    float* out = (float*)d_out;

    static int smem_set = 0;
    if (!smem_set) {
        cudaFuncSetAttribute(k_loop, cudaFuncAttributeMaxDynamicSharedMemorySize,
                             LOOP_SMEM);
        smem_set = 1;
    }

    int packBlocks = (WCP_END + 255) / 256;
    k_init<<<(NN * NH + 255) / 256, 256>>>();
    k_deg<<<(E + 255) / 256, 256>>>(dst, E);
    k_scan<<<1, 1024>>>(E);
    k_fill<<<(E + 255) / 256, 256>>>(src, dst, E);
    k_xconv<<<XC_BLOCKS, 256>>>(x);
    k_pack<<<packBlocks, 256>>>(Wi, bi, Wf, bf, Wo, bo, Wg, bg, W1, Wc);

    k_loop<<<GRID_LOOP, 256, LOOP_SMEM>>>();

    k_gemm<<<dim3((NN + 63) / 64, 4), 256>>>(0, nullptr, nullptr, NN, NH, 256);
    k_edge_nodes<<<NN / 8, 256>>>(b1);
    k_prop2<<<NN / 8, 256>>>();
    k_gemm<<<dim3((NN + 63) / 64, 1), 256>>>(1, bc, out, NN, NH, NOUT);
}

// round 17
// speedup vs baseline: 1.5171x; 1.0985x over previous
#include <cuda_runtime.h>
#include <cuda_fp16.h>
#include <cstdint>

#define NN   10000
#define TT   64
#define NIN  64
#define NH   128
#define NOUT 64
#define KTOT 192
#define EMAX 160000
#define GRID_LOOP 296          // 2 CTAs/SM, co-resident for the global barrier
#define ROWS_PER_CTA 34        // ceil(10000/296)
#define NTILES 628             // 157 m-tiles (BM=64) x 4 n-tiles (BN=128)
#define STAGE_BYTES 24576      // Ah 8K | Bh 16K
#define LOOP_SMEM 49152        // 2 stage buffers; epilogue reuses buffer 0 (33.8KB)
#define XC_BLOCKS 80000        // TT*NN*NIN/2/256

// ---------------- device scratch ----------------
__device__ float d_dinv[NN];
__device__ int   d_deg[NN];
__device__ int   d_off[NN + 1];
__device__ int   d_fill[NN];
__device__ int   d_adj[EMAX];
__device__ int   d_barCnt;
__device__ __half d_xh[(size_t)TT * NN * NIN];   // pre-scaled fp16 x (dinv*x)
__device__ __half d_Pxth[NN * NIN];              // per-step Px (fp16)
__device__ __half d_Phh[NN * NH];                // per-step Ph (fp16)
__device__ float d_h[NN * NH];
__device__ float d_c[NN * NH];
__device__ __half d_hsbuf[2][NN * NH];           // fp16 pre-scaled hidden state
__device__ __half d_Wpk[3 * 512 * 64];           // [chunk64][n=j*4+g][k64]
__device__ float d_bpk[512];                 // [j*4+g]
__device__ float d_W1p[NH * 256];
__device__ float d_Wcp[NH * NOUT];
__device__ float d_HaHb[NN * 256];
__device__ float d_nodes[NN * NH];
__device__ float d_Pn[NN * NH];

// ---------------- helpers ----------------
__device__ __forceinline__ uint32_t smem_u32(const void* p) {
    uint32_t a;
    asm("{ .reg .u64 t; cvta.to.shared.u64 t, %1; cvt.u32.u64 %0, t; }" : "=r"(a) : "l"(p));
    return a;
}
__device__ __forceinline__ uint32_t pkh(__half a, __half b) {
    return (uint32_t)__half_as_ushort(a) | ((uint32_t)__half_as_ushort(b) << 16);
}
__device__ __forceinline__ float2 h2f2(uint32_t u) {
    __half2 h = *reinterpret_cast<__half2*>(&u);
    return __half22float2(h);
}
__device__ __forceinline__ void cp16(uint32_t dst, const void* src, uint32_t srcsize) {
    asm volatile("cp.async.ca.shared.global [%0], [%1], 16, %2;"
                 :: "r"(dst), "l"(src), "r"(srcsize) : "memory");
}
__device__ __forceinline__ void cp16cg(uint32_t dst, const void* src, uint32_t srcsize) {
    asm volatile("cp.async.cg.shared.global [%0], [%1], 16, %2;"
                 :: "r"(dst), "l"(src), "r"(srcsize) : "memory");
}
__device__ __forceinline__ void cp_commit() {
    asm volatile("cp.async.commit_group;" ::: "memory");
}
__device__ __forceinline__ void cp_wait1() {
    asm volatile("cp.async.wait_group 1;" ::: "memory");
}
__device__ __forceinline__ void cp_wait0() {
    asm volatile("cp.async.wait_group 0;" ::: "memory");
}
__device__ __forceinline__ void ldsm4(uint32_t* r, uint32_t addr) {
    asm volatile("ldmatrix.sync.aligned.m8n8.x4.shared.b16 {%0,%1,%2,%3}, [%4];"
                 : "=r"(r[0]), "=r"(r[1]), "=r"(r[2]), "=r"(r[3]) : "r"(addr));
}
__device__ __forceinline__ void mma16816(float* c, const uint32_t* a, const uint32_t* b) {
    asm volatile("mma.sync.aligned.m16n8k16.row.col.f32.f16.f16.f32 "
                 "{%0,%1,%2,%3}, {%4,%5,%6,%7}, {%8,%9}, {%0,%1,%2,%3};"
                 : "+f"(c[0]), "+f"(c[1]), "+f"(c[2]), "+f"(c[3])
                 : "r"(a[0]), "r"(a[1]), "r"(a[2]), "r"(a[3]), "r"(b[0]), "r"(b[1]));
}
__device__ __forceinline__ float sigf(float x) { return 1.0f / (1.0f + __expf(-x)); }

// generation-free global barrier: monotone counter, target = bidx * GRID_LOOP
__device__ __forceinline__ void gbar(int bidx) {
    __syncthreads();
    if (threadIdx.x == 0) {
        __threadfence();
        atomicAdd(&d_barCnt, 1);
        int target = bidx * GRID_LOOP;
        int v;
        do {
            asm volatile("ld.global.cg.b32 %0, [%1];" : "=r"(v) : "l"(&d_barCnt));
            if (v < target) __nanosleep(64);
        } while (v < target);
        __threadfence();
    }
    __syncthreads();
}

// ---------------- setup kernels ----------------
__global__ void k_init() {
    int i = blockIdx.x * blockDim.x + threadIdx.x;
    if (i < NN * NH) { d_c[i] = 0.f; d_hsbuf[0][i] = __float2half_rn(0.f); }
    if (i < NN)      { d_deg[i] = 1; d_fill[i] = 0; }
    if (i == 0)      d_barCnt = 0;
}

__global__ void k_deg(const int* __restrict__ dst, int E) {
    int i = blockIdx.x * blockDim.x + threadIdx.x;
    if (i < E) atomicAdd(&d_deg[dst[i]], 1);
}

// scan (CSR offsets) + dinv in one kernel
__global__ void k_scan(int E) {
    __shared__ int ssum[1024];
    int tid = threadIdx.x;
    int loc[10]; int run = 0;
#pragma unroll
    for (int i = 0; i < 10; i++) {
        int v = tid * 10 + i;
        int c = (v < NN) ? (d_deg[v] - 1) : 0;
        loc[i] = run; run += c;
    }
    ssum[tid] = run; __syncthreads();
    for (int off = 1; off < 1024; off <<= 1) {
        int t = (tid >= off) ? ssum[tid - off] : 0;
        __syncthreads();
        ssum[tid] += t;
        __syncthreads();
    }
    int base = (tid == 0) ? 0 : ssum[tid - 1];
#pragma unroll
    for (int i = 0; i < 10; i++) {
        int v = tid * 10 + i;
        if (v < NN) {
            d_off[v] = base + loc[i];
            d_dinv[v] = rsqrtf((float)d_deg[v]);
        }
    }
    if (tid == 0) d_off[NN] = E;
}

__global__ void k_fill(const int* __restrict__ src, const int* __restrict__ dst, int E) {
    int i = blockIdx.x * blockDim.x + threadIdx.x;
    if (i < E) {
        int v = dst[i];
        int p = d_off[v] + atomicAdd(&d_fill[v], 1);
        d_adj[p] = src[i];
    }
}

// convert x to PRE-SCALED fp16 once: xh[t,v,:] = half(dinv[v] * x[t,v,:])
__global__ void k_xconv(const float* __restrict__ x) {
    size_t i = ((size_t)blockIdx.x * 256 + threadIdx.x) * 2;
    int v = (int)((i >> 6) % NN);
    float dv = d_dinv[v];
    float2 val = *(const float2*)&x[i];
    *(__half2*)&d_xh[i] = __floats2half2_rn(dv * val.x, dv * val.y);
}

// weight packing (fp16, [j*4+g] column order) + decoder weights
#define WPK_N   98304
#define BPK_END (WPK_N + 512)
#define W1P_END (BPK_END + NH * 256)
#define WCP_END (W1P_END + NH * NOUT)
__global__ void k_pack(const float* __restrict__ Wi, const float* __restrict__ bi,
                       const float* __restrict__ Wf, const float* __restrict__ bf,
                       const float* __restrict__ Wo, const float* __restrict__ bo,
                       const float* __restrict__ Wg, const float* __restrict__ bg,
                       const float* __restrict__ W1, const float* __restrict__ Wc) {
    int idx = blockIdx.x * 256 + threadIdx.x;
    if (idx < WPK_N) {
        int c = idx / 32768;
        int r2 = idx % 32768;
        int n = r2 >> 6, kk = r2 & 63;
        int j = n >> 2, g = n & 3, k = c * 64 + kk;
        const float* W = (g == 0) ? Wi : (g == 1) ? Wf : (g == 2) ? Wo : Wg;
        d_Wpk[idx] = __float2half_rn(W[j * KTOT + k]);
    } else if (idx < BPK_END) {
        int i = idx - WPK_N;
        int j = i >> 2, g = i & 3;
        const float* b = (g == 0) ? bi : (g == 1) ? bf : (g == 2) ? bo : bg;
        d_bpk[i] = b[j];
    } else if (idx < W1P_END) {
        int r = idx - BPK_END;
        int k = r / 256, cc = r % 256;
        d_W1p[r] = W1[(cc & 127) * 256 + (cc >> 7) * 128 + k];
    } else if (idx < WCP_END) {
        int r = idx - W1P_END;
        int k = r / NOUT, j = r % NOUT;
        d_Wcp[r] = Wc[j * NH + k];
    }
}

// ---------------- persistent loop kernel --------------------------------------
// One stage per K chunk c (0..2): {Ah 8K, Bh 16K}; single fp16 pass per chunk.
__device__ __forceinline__ void loadStage(uint32_t sbse, int buf, int c,
                                          int m0, int n0, int tid) {
    uint32_t Ab = sbse + buf * STAGE_BYTES;
    // A: 512 x cp16 — step-varying: bypass L1
#pragma unroll
    for (int rep = 0; rep < 2; rep++) {
        int q = tid + rep * 256;
        int row = q >> 3, kg = q & 7;
        uint32_t ok = (m0 + row < NN) ? 16 : 0;
        uint32_t dst = Ab + row * 128 + ((kg ^ (row & 7)) << 4);
        const __half* src;
        if (c == 0) src = d_Pxth + (size_t)(m0 + row) * 64 + kg * 8;
        else        src = d_Phh + (size_t)(m0 + row) * 128 + (c - 1) * 64 + kg * 8;
        cp16cg(dst, src, ok);
    }
    // B: 1024 x cp16 — immutable: L1-cacheable
#pragma unroll
    for (int rep = 0; rep < 4; rep++) {
        int q = tid + rep * 256;
        int nr = q >> 3, kg = q & 7;
        uint32_t dst = Ab + 8192 + nr * 128 + ((kg ^ (nr & 7)) << 4);
        const __half* src = d_Wpk + (size_t)(c * 512 + n0 + nr) * 64 + kg * 8;
        cp16(dst, src, 16);
    }
}

__global__ void __launch_bounds__(256, 2) k_loop() {
    extern __shared__ char smem[];
    const uint32_t sbse = smem_u32(smem);
    const int tid = threadIdx.x, lane = tid & 31, w = tid >> 5;
    const int cta = blockIdx.x;
    const int g = lane >> 3, lr = lane & 7;
    const int wm = (w >> 2) * 32, wn = (w & 3) * 32;

    for (int t = 0; t < TT; t++) {
        const __half* hsr = d_hsbuf[t & 1];
        __half* hsw = d_hsbuf[(t & 1) ^ 1];
        const __half* xt = d_xh + (size_t)t * NN * NIN;

        // ---- prop phase: combined 192-feature gather (hs 128 + x_t 64) ----
        for (int rl = w; rl < ROWS_PER_CTA; rl += 8) {
            int m = cta * ROWS_PER_CTA + rl;
            if (m < NN) {
                int f4 = lane * 4, f2 = lane * 2;
                uint2 raw = __ldcg((const uint2*)&hsr[m * NH + f4]);
                float2 s0f = h2f2(raw.x), s1f = h2f2(raw.y);
                float4 a = make_float4(s0f.x, s0f.y, s1f.x, s1f.y);
                float2 ax = h2f2(__ldcg((const unsigned int*)&xt[m * NIN + f2]));
                int e = d_off[m], end = d_off[m + 1];
                for (; e + 1 < end; e += 2) {
                    int n0i = d_adj[e], n1i = d_adj[e + 1];
                    uint2 r0 = __ldcg((const uint2*)&hsr[n0i * NH + f4]);
                    uint2 r1 = __ldcg((const uint2*)&hsr[n1i * NH + f4]);
                    unsigned int x0 = __ldcg((const unsigned int*)&xt[n0i * NIN + f2]);
                    unsigned int x1 = __ldcg((const unsigned int*)&xt[n1i * NIN + f2]);
                    float2 a0 = h2f2(r0.x), b0 = h2f2(r0.y);
                    float2 a1 = h2f2(r1.x), b1 = h2f2(r1.y);
                    float2 xa = h2f2(x0), xb = h2f2(x1);
                    a.x += a0.x + a1.x; a.y += a0.y + a1.y;
                    a.z += b0.x + b1.x; a.w += b0.y + b1.y;
                    ax.x += xa.x + xb.x; ax.y += xa.y + xb.y;
                }
                if (e < end) {
                    int n0i = d_adj[e];
                    uint2 r0 = __ldcg((const uint2*)&hsr[n0i * NH + f4]);
                    unsigned int x0 = __ldcg((const unsigned int*)&xt[n0i * NIN + f2]);
                    float2 a0 = h2f2(r0.x), b0 = h2f2(r0.y);
                    float2 xa = h2f2(x0);
                    a.x += a0.x; a.y += a0.y; a.z += b0.x; a.w += b0.y;
                    ax.x += xa.x; ax.y += xa.y;
                }
                float dv = d_dinv[m];
                a.x *= dv; a.y *= dv; a.z *= dv; a.w *= dv;
                ax.x *= dv; ax.y *= dv;
                __half h0 = __float2half_rn(a.x), h1 = __float2half_rn(a.y);
                __half h2 = __float2half_rn(a.z), h3 = __float2half_rn(a.w);
                *(uint2*)&d_Phh[m * NH + f4] = make_uint2(pkh(h0, h1), pkh(h2, h3));
                __half xh0 = __float2half_rn(ax.x), xh1 = __float2half_rn(ax.y);
                *(uint32_t*)&d_Pxth[m * NIN + f2] = pkh(xh0, xh1);
            }
        }
        gbar(2 * t + 1);

        // ---- GEMM + LSTM phase ----
        for (int tile = cta; tile < NTILES; tile += GRID_LOOP) {
            int m0 = (tile >> 2) * 64;
            int n0 = (tile & 3) * 128;

            float acc[2][4][4];
#pragma unroll
            for (int i = 0; i < 2; i++)
#pragma unroll
                for (int j = 0; j < 4; j++)
#pragma unroll
                    for (int q = 0; q < 4; q++) acc[i][j][q] = 0.f;

            loadStage(sbse, 0, 0, m0, n0, tid); cp_commit();
            loadStage(sbse, 1, 1, m0, n0, tid); cp_commit();

#pragma unroll
            for (int c = 0; c < 3; c++) {
                if (c < 2) cp_wait1(); else cp_wait0();
                __syncthreads();
                uint32_t Ab = sbse + (c & 1) * STAGE_BYTES;
#pragma unroll
                for (int ks = 0; ks < 4; ks++) {
                    uint32_t afh[2][4], bfh[2][4];
#pragma unroll
                    for (int mt = 0; mt < 2; mt++) {
                        int ar = wm + mt * 16 + (g & 1) * 8 + lr;
                        int akg = ks * 2 + (g >> 1);
                        uint32_t off = ar * 128 + ((akg ^ (ar & 7)) << 4);
                        ldsm4(afh[mt], Ab + off);
                    }
#pragma unroll
                    for (int ns2 = 0; ns2 < 2; ns2++) {
                        int br = wn + ns2 * 16 + (g >> 1) * 8 + lr;
                        int bkg = ks * 2 + (g & 1);
                        uint32_t off = br * 128 + ((bkg ^ (br & 7)) << 4);
                        ldsm4(bfh[ns2], Ab + 8192 + off);
                    }
#pragma unroll
                    for (int mt = 0; mt < 2; mt++)
#pragma unroll
                        for (int nt = 0; nt < 4; nt++)
                            mma16816(acc[mt][nt], afh[mt], &bfh[nt >> 1][(nt & 1) * 2]);
                }
                __syncthreads();
                if (c == 0) { loadStage(sbse, 0, 2, m0, n0, tid); cp_commit(); }
            }

            // stage accumulators to smem [64][132] (reuses stage buffers)
            float* Cs = (float*)smem;
#pragma unroll
            for (int mt = 0; mt < 2; mt++)
#pragma unroll
                for (int nt = 0; nt < 4; nt++) {
                    int r = wm + mt * 16 + (lane >> 2);
                    int col = wn + nt * 8 + (lane & 3) * 2;
                    *(float2*)&Cs[r * 132 + col] =
                        make_float2(acc[mt][nt][0], acc[mt][nt][1]);
                    *(float2*)&Cs[(r + 8) * 132 + col] =
                        make_float2(acc[mt][nt][2], acc[mt][nt][3]);
                }
            __syncthreads();

            // fused LSTM epilogue: 64 rows x 32 j's
#pragma unroll
            for (int it = 0; it < 8; it++) {
                int idx = it * 256 + tid;
                int mloc = idx >> 5, jloc = idx & 31;
                int m = m0 + mloc;
                if (m < NN) {
                    float4 pre = *(const float4*)&Cs[mloc * 132 + jloc * 4];
                    int j = (n0 >> 2) + jloc;
                    float4 bb = *(const float4*)&d_bpk[j * 4];
                    float i_ = sigf(pre.x + bb.x);
                    float f_ = sigf(pre.y + bb.y);
                    float o_ = sigf(pre.z + bb.z);
                    float gg = tanhf(pre.w + bb.w);
                    int ci = m * NH + j;
                    float cn = f_ * d_c[ci] + i_ * gg;   // c is CTA-local (fixed map)
                    float hh = o_ * tanhf(cn);
                    d_c[ci] = cn;
                    hsw[ci] = __float2half_rn(d_dinv[m] * hh);
                    if (t == TT - 1) d_h[ci] = hh;
                }
            }
            __syncthreads();
        }
        gbar(2 * t + 2);
    }
}

// ---------------- decoder ----------------
__global__ void k_gemm(int sel, const float* __restrict__ bias, float* __restrict__ Cout,
                       int M, int K, int N) {
    __shared__ __align__(16) float As[16][64];
    __shared__ __align__(16) float Bs[16][64];
    const float* A = sel ? d_Pn  : d_h;
    const float* B = sel ? d_Wcp : d_W1p;
    float*       C = sel ? Cout  : d_HaHb;
    int tid = threadIdx.x;
    int tx = tid & 15, ty = tid >> 4;
    int m0 = blockIdx.x * 64, n0 = blockIdx.y * 64;
    float acc[4][4] = {};
    int lrow = tid >> 2, lkp = (tid & 3) * 4;
    int bk = tid >> 4, bcc = (tid & 15) * 4;
    for (int kc = 0; kc < K; kc += 16) {
        float4 av = make_float4(0.f, 0.f, 0.f, 0.f);
        int grow = m0 + lrow;
        if (grow < M) av = *(const float4*)&A[grow * K + kc + lkp];
        As[lkp + 0][lrow] = av.x; As[lkp + 1][lrow] = av.y;
        As[lkp + 2][lrow] = av.z; As[lkp + 3][lrow] = av.w;
        float4 bv = *(const float4*)&B[(kc + bk) * N + n0 + bcc];
        *(float4*)&Bs[bk][bcc] = bv;
        __syncthreads();
#pragma unroll
        for (int k = 0; k < 16; k++) {
            float4 a = *(const float4*)&As[k][ty * 4];
            float4 b = *(const float4*)&Bs[k][tx * 4];
            float ar[4] = {a.x, a.y, a.z, a.w};
            float br[4] = {b.x, b.y, b.z, b.w};
#pragma unroll
            for (int i = 0; i < 4; i++)
#pragma unroll
                for (int j = 0; j < 4; j++) acc[i][j] = fmaf(ar[i], br[j], acc[i][j]);
        }
        __syncthreads();
    }
    float4 bb = make_float4(0.f, 0.f, 0.f, 0.f);
    if (bias) bb = *(const float4*)&bias[n0 + tx * 4];
#pragma unroll
    for (int i = 0; i < 4; i++) {
        int m = m0 + ty * 4 + i;
        if (m >= M) continue;
        float4 o = make_float4(acc[i][0] + bb.x, acc[i][1] + bb.y,
                               acc[i][2] + bb.z, acc[i][3] + bb.w);
        *(float4*)&C[m * N + n0 + tx * 4] = o;
    }
}

__global__ void k_edge_nodes(const float* __restrict__ b1) {
    int w = blockIdx.x * 8 + (threadIdx.x >> 5);
    if (w >= NN) return;
    int l4 = (threadIdx.x & 31) * 4;
    float4 ha = *(const float4*)&d_HaHb[w * 256 + l4];
    float4 bb = *(const float4*)&b1[l4];
    ha.x += bb.x; ha.y += bb.y; ha.z += bb.z; ha.w += bb.w;
    float4 acc = make_float4(0.f, 0.f, 0.f, 0.f);
    int e = d_off[w], end = d_off[w + 1];
#pragma unroll 2
    for (; e < end; e++) {
        int s = d_adj[e];
        float4 hb = *(const float4*)&d_HaHb[s * 256 + 128 + l4];
        acc.x += fmaxf(ha.x + hb.x, 0.f);
        acc.y += fmaxf(ha.y + hb.y, 0.f);
        acc.z += fmaxf(ha.z + hb.z, 0.f);
        acc.w += fmaxf(ha.w + hb.w, 0.f);
    }
    *(float4*)&d_nodes[w * NH + l4] = acc;
}

__global__ void k_prop2() {
    int w = blockIdx.x * 8 + (threadIdx.x >> 5);
    if (w >= NN) return;
    int l4 = (threadIdx.x & 31) * 4;
    float dv = d_dinv[w];
    float4 sv = *(const float4*)&d_nodes[w * NH + l4];
    float4 acc = make_float4(dv * sv.x, dv * sv.y, dv * sv.z, dv * sv.w);
    int e = d_off[w], end = d_off[w + 1];
#pragma unroll 2
    for (; e < end; e++) {
        int s = d_adj[e];
        float ds = d_dinv[s];
        float4 v0 = *(const float4*)&d_nodes[s * NH + l4];
        acc.x += ds * v0.x; acc.y += ds * v0.y;
        acc.z += ds * v0.z; acc.w += ds * v0.w;
    }
    acc.x *= dv; acc.y *= dv; acc.z *= dv; acc.w *= dv;
    *(float4*)&d_Pn[w * NH + l4] = acc;
}

// ---------------- host launcher ----------------
extern "C" void kernel_launch(void* const* d_in, const int* in_sizes, int n_in,
                              void* d_out, int out_size) {
    const float* x  = (const float*)d_in[0];
    const int*   ei = (const int*)d_in[1];
    const int    E  = in_sizes[2];
    const int* src = ei;
    const int* dst = ei + E;
    const float* Wi = (const float*)d_in[4];
    const float* bi = (const float*)d_in[5];
    const float* Wf = (const float*)d_in[6];
    const float* bf = (const float*)d_in[7];
    const float* Wo = (const float*)d_in[8];
    const float* bo = (const float*)d_in[9];
    const float* Wg = (const float*)d_in[10];
    const float* bg = (const float*)d_in[11];
    const float* W1 = (const float*)d_in[12];
    const float* b1 = (const float*)d_in[13];
    const float* Wc = (const float*)d_in[14];
    const float* bc = (const float*)d_in[15];
    float* out = (float*)d_out;

    static int smem_set = 0;
    if (!smem_set) {
        cudaFuncSetAttribute(k_loop, cudaFuncAttributeMaxDynamicSharedMemorySize,
                             LOOP_SMEM);
        smem_set = 1;
    }

    int packBlocks = (WCP_END + 255) / 256;
    k_init<<<(NN * NH + 255) / 256, 256>>>();
    k_deg<<<(E + 255) / 256, 256>>>(dst, E);
    k_scan<<<1, 1024>>>(E);
    k_fill<<<(E + 255) / 256, 256>>>(src, dst, E);
    k_xconv<<<XC_BLOCKS, 256>>>(x);
    k_pack<<<packBlocks, 256>>>(Wi, bi, Wf, bf, Wo, bo, Wg, bg, W1, Wc);

    k_loop<<<GRID_LOOP, 256, LOOP_SMEM>>>();

    k_gemm<<<dim3((NN + 63) / 64, 4), 256>>>(0, nullptr, nullptr, NN, NH, 256);
    k_edge_nodes<<<NN / 8, 256>>>(b1);
    k_prop2<<<NN / 8, 256>>>();
    k_gemm<<<dim3((NN + 63) / 64, 1), 256>>>(1, bc, out, NN, NH, NOUT);
}